// round 1
// baseline (speedup 1.0000x reference)
#include <cuda_runtime.h>
#include <math.h>

#define BB 8
#define SS 1024
#define HH 768
#define TT 8
#define DDI 64
#define HIDD 128
#define KSP 8
#define NHEADS 2
#define NN 9
#define FF 256      // NHEADS*HIDD
#define OUTD 1024   // TT*2*DDI
#define KE 80       // 64 rope dims + 16 gaussian correction dims
#define NEGC 1000000000000.0f

// ------------------- device scratch (static, no runtime alloc) -------------------
__device__ float d_gfpart[BB * 8 * HH];
__device__ float d_enh[BB * FF];
__device__ float d_eW[BB * OUTD];
__device__ float d_cover[BB * SS];
__device__ float d_Y[(size_t)BB * SS * OUTD];          // 32 MB
__device__ float d_qext[(size_t)BB * TT * SS * KE];    // 21 MB
__device__ float d_kext[(size_t)BB * TT * SS * KE];    // 21 MB

// ------------------- kernel 0: partial sums for global_feat -------------------
__global__ void k_gfpart(const float* __restrict__ hidden) {
    int b = blockIdx.y, p = blockIdx.x;
    for (int c = threadIdx.x; c < HH; c += 256) {
        float acc = 0.f;
        const float* base = hidden + ((size_t)b * SS + (size_t)p * 128) * HH + c;
        #pragma unroll 4
        for (int s = 0; s < 128; s++) acc += base[(size_t)s * HH];
        d_gfpart[(b * 8 + p) * HH + c] = acc;
    }
}

// ------------------- kernel: cover counts -------------------
__global__ void k_cover(const int* __restrict__ spans) {
    int idx = blockIdx.x * 256 + threadIdx.x;
    if (idx >= BB * SS) return;
    int b = idx >> 10, s = idx & (SS - 1);
    const int* sp = spans + b * KSP * 3;
    float c = 0.f;
    #pragma unroll
    for (int k = 0; k < KSP; k++) {
        int st = sp[k * 3], en = sp[k * 3 + 1];
        c += (s >= st && s <= en) ? 1.f : 0.f;
    }
    d_cover[idx] = c;
}

// ------------------- GAT attention helper (runs in one block) -------------------
__device__ __forceinline__ void gat_attn(const float* __restrict__ hmat,  // NN*FF smem
                                         const float* __restrict__ avsrc,
                                         const float* __restrict__ avdst,
                                         const float* __restrict__ sAdj,
                                         float* sAS, float* sAD, float* sAttn, int tid) {
    if (tid < NN * NHEADS * 2) {
        int n = tid / (NHEADS * 2);
        int rem = tid % (NHEADS * 2);
        int head = rem % NHEADS;
        int isd = rem / NHEADS;
        const float* av = isd ? avdst : avsrc;
        float acc = 0.f;
        for (int f = 0; f < HIDD; f++) acc += hmat[n * FF + head * HIDD + f] * av[head * HIDD + f];
        if (isd) sAD[n * NHEADS + head] = acc;
        else     sAS[n * NHEADS + head] = acc;
    }
    __syncthreads();
    if (tid < NN * NHEADS) {
        int i = tid / NHEADS, head = tid % NHEADS;
        float sc[NN];
        float mx = -1e30f;
        #pragma unroll
        for (int j = 0; j < NN; j++) {
            float adj = sAdj[i * NN + j];
            float v;
            if (adj > 0.f) {
                float e = sAD[i * NHEADS + head] + sAS[j * NHEADS + head];
                e = (e >= 0.f) ? e : 0.2f * e;
                v = e + logf(adj);
            } else v = -1e30f;
            sc[j] = v;
            mx = fmaxf(mx, v);
        }
        float ssum = 0.f;
        #pragma unroll
        for (int j = 0; j < NN; j++) { float e = expf(sc[j] - mx); sc[j] = e; ssum += e; }
        float inv = 1.f / ssum;
        #pragma unroll
        for (int j = 0; j < NN; j++) sAttn[(i * NN + j) * NHEADS + head] = sc[j] * inv;
    }
    __syncthreads();
}

// ------------------- kernel: per-batch graph pipeline -------------------
__global__ void k_stage1(const float* __restrict__ hidden, const int* __restrict__ spans,
                         const float* __restrict__ W1, const float* __restrict__ asrc1,
                         const float* __restrict__ adst1, const float* __restrict__ b1,
                         const float* __restrict__ lng, const float* __restrict__ lnb,
                         const float* __restrict__ W2, const float* __restrict__ asrc2,
                         const float* __restrict__ adst2, const float* __restrict__ b2,
                         const float* __restrict__ dW) {
    int b = blockIdx.x;
    int tid = threadIdx.x;
    __shared__ float sN[NN * HH];
    __shared__ float sH[NN * FF];
    __shared__ float sG[NN * FF];
    __shared__ float sAdj[NN * NN];
    __shared__ float sAS[NN * NHEADS], sAD[NN * NHEADS];
    __shared__ float sAttn[NN * NN * NHEADS];
    __shared__ int sSp[KSP * 2];
    __shared__ float sRed[2];
    __shared__ float sWred[16];

    if (tid < KSP * 2) {
        int k = tid / 2, w = tid % 2;
        sSp[tid] = spans[(b * KSP + k) * 3 + w];
    }
    __syncthreads();

    // node features
    for (int c = tid; c < HH; c += 256) {
        float g = 0.f;
        #pragma unroll
        for (int p = 0; p < 8; p++) g += d_gfpart[(b * 8 + p) * HH + c];
        sN[c] = g * (1.f / (float)SS);
    }
    for (int k = 0; k < KSP; k++) {
        int st = sSp[k * 2], en = sSp[k * 2 + 1];
        float inv = 1.f / (float)(en - st + 1);
        for (int c = tid; c < HH; c += 256) {
            float a = 0.f;
            for (int s = st; s <= en; s++) a += hidden[((size_t)b * SS + s) * HH + c];
            sN[(1 + k) * HH + c] = a * inv;
        }
    }
    // adjacency
    if (tid < NN * NN) {
        int r = tid / NN, c = tid % NN;
        float v = 0.f;
        if (r == c) v += 1.f;
        if (c == 0 && r >= 1) v += 1.f;
        if (r == 0 && c >= 1) v += 1.f;
        if (r >= 1 && c >= 1 && r != c) {
            int i = r - 1, j = c - 1;
            int si = sSp[i * 2], ei = sSp[i * 2 + 1];
            int sj = sSp[j * 2], ej = sSp[j * 2 + 1];
            bool same = (sj == si) && (ej == ei);
            if ((sj <= si) && (ei <= ej) && !same) v += 2.f;
        }
        sAdj[tid] = v;
    }
    __syncthreads();

    // h1 = nodes @ W1
    {
        float acc[NN];
        #pragma unroll
        for (int n = 0; n < NN; n++) acc[n] = 0.f;
        for (int d = 0; d < HH; d++) {
            float w = W1[d * FF + tid];
            #pragma unroll
            for (int n = 0; n < NN; n++) acc[n] += sN[n * HH + d] * w;
        }
        #pragma unroll
        for (int n = 0; n < NN; n++) sH[n * FF + tid] = acc[n];
    }
    __syncthreads();
    gat_attn(sH, asrc1, adst1, sAdj, sAS, sAD, sAttn, tid);
    // out1 + b1, relu -> sG
    {
        int head = tid / HIDD;
        for (int i = 0; i < NN; i++) {
            float acc = b1[tid];
            #pragma unroll
            for (int j = 0; j < NN; j++) acc += sAttn[(i * NN + j) * NHEADS + head] * sH[j * FF + tid];
            sG[i * FF + tid] = fmaxf(acc, 0.f);
        }
    }
    __syncthreads();
    // layernorm per node
    for (int i = 0; i < NN; i++) {
        float v = sG[i * FF + tid];
        float s1 = v, s2 = v * v;
        #pragma unroll
        for (int o = 16; o > 0; o >>= 1) {
            s1 += __shfl_down_sync(0xffffffffu, s1, o);
            s2 += __shfl_down_sync(0xffffffffu, s2, o);
        }
        int wid = tid >> 5, lid = tid & 31;
        if (lid == 0) { sWred[wid] = s1; sWred[8 + wid] = s2; }
        __syncthreads();
        if (tid == 0) {
            float a = 0.f, q = 0.f;
            #pragma unroll
            for (int w = 0; w < 8; w++) { a += sWred[w]; q += sWred[8 + w]; }
            float mu = a / (float)FF;
            float var = q / (float)FF - mu * mu;
            sRed[0] = mu;
            sRed[1] = rsqrtf(var + 1e-5f);
        }
        __syncthreads();
        sG[i * FF + tid] = (v - sRed[0]) * sRed[1] * lng[tid] + lnb[tid];
        __syncthreads();
    }

    // h2 = g1 @ W2 -> sH
    {
        float acc[NN];
        #pragma unroll
        for (int n = 0; n < NN; n++) acc[n] = 0.f;
        for (int d = 0; d < FF; d++) {
            float w = W2[d * FF + tid];
            #pragma unroll
            for (int n = 0; n < NN; n++) acc[n] += sG[n * FF + d] * w;
        }
        #pragma unroll
        for (int n = 0; n < NN; n++) sH[n * FF + tid] = acc[n];
    }
    __syncthreads();
    gat_attn(sH, asrc2, adst2, sAdj, sAS, sAD, sAttn, tid);
    // out2 + b2, relu, mean over nodes -> enhanced
    {
        int head = tid / HIDD;
        float esum = 0.f;
        for (int i = 0; i < NN; i++) {
            float acc = b2[tid];
            #pragma unroll
            for (int j = 0; j < NN; j++) acc += sAttn[(i * NN + j) * NHEADS + head] * sH[j * FF + tid];
            esum += fmaxf(acc, 0.f);
        }
        float enh = esum * (1.f / (float)NN);
        d_enh[b * FF + tid] = enh;
        sG[tid] = enh;
    }
    __syncthreads();
    // eW[b, :] = enhanced @ dense_W[768:1024, :]
    for (int o = tid; o < OUTD; o += 256) {
        float acc = 0.f;
        for (int c = 0; c < FF; c++) acc += sG[c] * dW[(size_t)(HH + c) * OUTD + o];
        d_eW[b * OUTD + o] = acc;
    }
}

// ------------------- kernel: GEMM1 = hidden @ dense_W[0:768] + epilogue -------------------
__global__ void k_gemm1(const float* __restrict__ A, const float* __restrict__ Wt,
                        const float* __restrict__ db) {
    __shared__ float As[16][64];
    __shared__ float Bs[16][64];
    int tx = threadIdx.x & 15, ty = threadIdx.x >> 4;
    int m0 = blockIdx.y * 64, n0 = blockIdx.x * 64;
    int lrow = threadIdx.x >> 2;
    int lq = (threadIdx.x & 3) * 4;
    int bkr = threadIdx.x >> 6;
    int bkc = threadIdx.x & 63;
    float acc[4][4] = {};
    for (int kk = 0; kk < HH; kk += 16) {
        float4 av = *(const float4*)&A[(size_t)(m0 + lrow) * HH + kk + lq];
        As[lq + 0][lrow] = av.x; As[lq + 1][lrow] = av.y;
        As[lq + 2][lrow] = av.z; As[lq + 3][lrow] = av.w;
        #pragma unroll
        for (int r = 0; r < 4; r++)
            Bs[bkr * 4 + r][bkc] = Wt[(size_t)(kk + bkr * 4 + r) * OUTD + n0 + bkc];
        __syncthreads();
        #pragma unroll
        for (int d = 0; d < 16; d++) {
            float4 af = *(const float4*)&As[d][ty * 4];
            float4 bf = *(const float4*)&Bs[d][tx * 4];
            float avr[4] = {af.x, af.y, af.z, af.w};
            float bvr[4] = {bf.x, bf.y, bf.z, bf.w};
            #pragma unroll
            for (int i = 0; i < 4; i++)
                #pragma unroll
                for (int j = 0; j < 4; j++) acc[i][j] += avr[i] * bvr[j];
        }
        __syncthreads();
    }
    int r0 = m0 + ty * 4;
    int c0 = n0 + tx * 4;
    #pragma unroll
    for (int i = 0; i < 4; i++) {
        int r = r0 + i;
        int b = r >> 10;
        float cov = d_cover[r];
        float4 ew = *(const float4*)&d_eW[b * OUTD + c0];
        float4 dbv = *(const float4*)&db[c0];
        float4 res;
        res.x = acc[i][0] + cov * ew.x + dbv.x;
        res.y = acc[i][1] + cov * ew.y + dbv.y;
        res.z = acc[i][2] + cov * ew.z + dbv.z;
        res.w = acc[i][3] + cov * ew.w + dbv.w;
        *(float4*)&d_Y[(size_t)r * OUTD + c0] = res;
    }
}

// ------------------- kernel: RoPE + build extended operands -------------------
__global__ void k_build(const int* __restrict__ spans, const float* __restrict__ gc,
                        const float* __restrict__ gs, const float* __restrict__ gw,
                        const float* __restrict__ corr) {
    int idx = blockIdx.x * 256 + threadIdx.x;   // (b*T+t)*S + s
    int s = idx & (SS - 1);
    int t = (idx >> 10) & (TT - 1);
    int b = idx >> 13;
    const float* y = d_Y + ((size_t)(b << 10) + s) * OUTD + t * (2 * DDI);
    float* qo = d_qext + (size_t)idx * KE;
    float* ko = d_kext + (size_t)idx * KE;
    const float L2C = 0.41524101186092573f;  // log2(10000)/32
    float sf = (float)s;
    #pragma unroll
    for (int i = 0; i < DDI / 2; i++) {
        float inv = exp2f(-(float)i * L2C);
        float ang = sf * inv;
        float sv, cv;
        sincosf(ang, &sv, &cv);
        float2 q = *(const float2*)&y[2 * i];
        float2 k = *(const float2*)&y[DDI + 2 * i];
        float2 qr, kr;
        qr.x = q.x * cv - q.y * sv;
        qr.y = q.y * cv + q.x * sv;
        kr.x = k.x * cv - k.y * sv;
        kr.y = k.y * cv + k.x * sv;
        *(float2*)&qo[2 * i] = qr;
        *(float2*)&ko[2 * i] = kr;
    }
    const int* sp = spans + b * KSP * 3;
    float g0w = gw[0], g1w = gw[1];
    float g0c = gc[0], g1c = gc[1];
    float g0si = 1.f / gs[0], g1si = 1.f / gs[1];
    #pragma unroll
    for (int kk = 0; kk < KSP; kk++) {
        int st = sp[kk * 3], en = sp[kk * 3 + 1], et = sp[kk * 3 + 2];
        float ct = corr[et * TT + t];
        float d0 = (sf - (float)st - g0c) * g0si;
        float d1 = (sf - (float)st - g1c) * g1si;
        float e0 = (sf - (float)en - g0c) * g0si;
        float e1 = (sf - (float)en - g1c) * g1si;
        qo[DDI + kk * 2 + 0] = ct * g0w * expf(-0.5f * d0 * d0);
        qo[DDI + kk * 2 + 1] = ct * g1w * expf(-0.5f * d1 * d1);
        ko[DDI + kk * 2 + 0] = g0w * expf(-0.5f * e0 * e0);
        ko[DDI + kk * 2 + 1] = g1w * expf(-0.5f * e1 * e1);
    }
}

// ------------------- kernel: GEMM2 (batched 1024x1024x80) + mask epilogue -------------------
__global__ void k_gemm2(const float* __restrict__ mask, float* __restrict__ out) {
    __shared__ float As[16][64];
    __shared__ float Bs[16][64];
    int bt = blockIdx.z;
    int b = bt >> 3;
    const float* Ab = d_qext + (size_t)bt * SS * KE;
    const float* Bb = d_kext + (size_t)bt * SS * KE;
    int m0 = blockIdx.y * 64, n0 = blockIdx.x * 64;
    int tx = threadIdx.x & 15, ty = threadIdx.x >> 4;
    int lrow = threadIdx.x >> 2;
    int lq = (threadIdx.x & 3) * 4;
    float acc[4][4] = {};
    for (int kk = 0; kk < KE; kk += 16) {
        float4 av = *(const float4*)&Ab[(size_t)(m0 + lrow) * KE + kk + lq];
        float4 bv = *(const float4*)&Bb[(size_t)(n0 + lrow) * KE + kk + lq];
        As[lq + 0][lrow] = av.x; As[lq + 1][lrow] = av.y;
        As[lq + 2][lrow] = av.z; As[lq + 3][lrow] = av.w;
        Bs[lq + 0][lrow] = bv.x; Bs[lq + 1][lrow] = bv.y;
        Bs[lq + 2][lrow] = bv.z; Bs[lq + 3][lrow] = bv.w;
        __syncthreads();
        #pragma unroll
        for (int d = 0; d < 16; d++) {
            float4 af = *(const float4*)&As[d][ty * 4];
            float4 bf = *(const float4*)&Bs[d][tx * 4];
            float avr[4] = {af.x, af.y, af.z, af.w};
            float bvr[4] = {bf.x, bf.y, bf.z, bf.w};
            #pragma unroll
            for (int i = 0; i < 4; i++)
                #pragma unroll
                for (int j = 0; j < 4; j++) acc[i][j] += avr[i] * bvr[j];
        }
        __syncthreads();
    }
    int mg0 = m0 + ty * 4, ng0 = n0 + tx * 4;
    float pad[4];
    #pragma unroll
    for (int j = 0; j < 4; j++) pad[j] = mask[b * SS + ng0 + j];
    #pragma unroll
    for (int i = 0; i < 4; i++) {
        int m = mg0 + i;
        float4 res;
        float v[4];
        #pragma unroll
        for (int j = 0; j < 4; j++) {
            int n = ng0 + j;
            float p = pad[j];
            float val = acc[i][j] * p - (1.f - p) * NEGC;
            if (m > n) val -= NEGC;
            v[j] = val * 0.125f;
        }
        res.x = v[0]; res.y = v[1]; res.z = v[2]; res.w = v[3];
        *(float4*)&out[((size_t)bt * SS + m) * SS + ng0] = res;
    }
}

// ------------------- launch -------------------
extern "C" void kernel_launch(void* const* d_in, const int* in_sizes, int n_in,
                              void* d_out, int out_size) {
    const float* hidden = (const float*)d_in[0];
    const float* amask  = (const float*)d_in[1];
    const int*   spans  = (const int*)d_in[2];
    const float* W1     = (const float*)d_in[3];
    const float* asrc1  = (const float*)d_in[4];
    const float* adst1  = (const float*)d_in[5];
    const float* b1     = (const float*)d_in[6];
    const float* lng    = (const float*)d_in[7];
    const float* lnb    = (const float*)d_in[8];
    const float* W2     = (const float*)d_in[9];
    const float* asrc2  = (const float*)d_in[10];
    const float* adst2  = (const float*)d_in[11];
    const float* b2     = (const float*)d_in[12];
    const float* dW     = (const float*)d_in[13];
    const float* db     = (const float*)d_in[14];
    const float* gc     = (const float*)d_in[15];
    const float* gsg    = (const float*)d_in[16];
    const float* gwt    = (const float*)d_in[17];
    const float* corr   = (const float*)d_in[18];
    float* out = (float*)d_out;

    k_gfpart<<<dim3(8, BB), 256>>>(hidden);
    k_cover<<<(BB * SS + 255) / 256, 256>>>(spans);
    k_stage1<<<BB, 256>>>(hidden, spans, W1, asrc1, adst1, b1, lng, lnb,
                          W2, asrc2, adst2, b2, dW);
    k_gemm1<<<dim3(OUTD / 64, (BB * SS) / 64), 256>>>(hidden, dW, db);
    k_build<<<(BB * TT * SS) / 256, 256>>>(spans, gc, gsg, gwt, corr);
    k_gemm2<<<dim3(SS / 64, SS / 64, BB * TT), 256>>>(amask, out);
}

// round 4
// speedup vs baseline: 2.2141x; 2.2141x over previous
#include <cuda_runtime.h>
#include <cuda_bf16.h>
#include <math.h>
#include <cstdint>
#include <cstddef>

#define BB 8
#define SS 1024
#define HH 768
#define TT 8
#define DDI 64
#define HIDD 128
#define KSP 8
#define NHEADS 2
#define NN 9
#define FF 256      // NHEADS*HIDD
#define OUTD 1024   // TT*2*DDI
#define KEP 96      // 64 rope + 16 gaussian + 16 zero pad (mult of 32)
#define NEGC 1000000000000.0f

// ------------------- device scratch -------------------
__device__ float d_gfpart[BB * 8 * HH];
__device__ float d_eW[BB * OUTD];
__device__ float d_cover[BB * SS];
__device__ float d_Y[(size_t)BB * SS * OUTD];                    // 32 MB fp32
__device__ __nv_bfloat16 d_hidbf[(size_t)BB * SS * HH];          // 12.6 MB
__device__ __nv_bfloat16 d_wbf[(size_t)OUTD * HH];               // W^T bf16 [n][k]
__device__ __nv_bfloat16 d_qext[(size_t)BB * TT * SS * KEP];     // 12.6 MB
__device__ __nv_bfloat16 d_kext[(size_t)BB * TT * SS * KEP];

__device__ __forceinline__ uint32_t smem_u32(const void* p) {
    uint32_t a;
    asm("{ .reg .u64 t; cvta.to.shared.u64 t, %1; cvt.u32.u64 %0, t; }" : "=r"(a) : "l"(p));
    return a;
}

// ------------------- conversion kernels -------------------
__global__ void k_cvthid(const float* __restrict__ h) {
    int i = (blockIdx.x * 256 + threadIdx.x) * 4;
    float4 v = *(const float4*)&h[i];
    __nv_bfloat162* o = (__nv_bfloat162*)&d_hidbf[i];
    o[0] = __floats2bfloat162_rn(v.x, v.y);
    o[1] = __floats2bfloat162_rn(v.z, v.w);
}

__global__ void k_cvtW(const float* __restrict__ W) {   // (768,1024) -> bf16 [1024][768]
    __shared__ float t[32][33];
    int k0 = blockIdx.y * 32, n0 = blockIdx.x * 32;
    int tx = threadIdx.x, ty = threadIdx.y;
    #pragma unroll
    for (int i = 0; i < 32; i += 8)
        t[ty + i][tx] = W[(size_t)(k0 + ty + i) * OUTD + n0 + tx];
    __syncthreads();
    #pragma unroll
    for (int i = 0; i < 32; i += 8)
        d_wbf[(size_t)(n0 + ty + i) * HH + k0 + tx] = __float2bfloat16(t[tx][ty + i]);
}

// ------------------- kernel 0: partial sums for global_feat -------------------
__global__ void k_gfpart(const float* __restrict__ hidden) {
    int b = blockIdx.y, p = blockIdx.x;
    for (int c = threadIdx.x; c < HH; c += 256) {
        float acc = 0.f;
        const float* base = hidden + ((size_t)b * SS + (size_t)p * 128) * HH + c;
        #pragma unroll 4
        for (int s = 0; s < 128; s++) acc += base[(size_t)s * HH];
        d_gfpart[(b * 8 + p) * HH + c] = acc;
    }
}

// ------------------- cover counts -------------------
__global__ void k_cover(const int* __restrict__ spans) {
    int idx = blockIdx.x * 256 + threadIdx.x;
    if (idx >= BB * SS) return;
    int b = idx >> 10, s = idx & (SS - 1);
    const int* sp = spans + b * KSP * 3;
    float c = 0.f;
    #pragma unroll
    for (int k = 0; k < KSP; k++) {
        int st = sp[k * 3], en = sp[k * 3 + 1];
        c += (s >= st && s <= en) ? 1.f : 0.f;
    }
    d_cover[idx] = c;
}

// ------------------- GAT attention helper -------------------
__device__ __forceinline__ void gat_attn(const float* __restrict__ hmat,
                                         const float* __restrict__ avsrc,
                                         const float* __restrict__ avdst,
                                         const float* __restrict__ sAdj,
                                         float* sAS, float* sAD, float* sAttn, int tid) {
    if (tid < NN * NHEADS * 2) {
        int n = tid / (NHEADS * 2);
        int rem = tid % (NHEADS * 2);
        int head = rem % NHEADS;
        int isd = rem / NHEADS;
        const float* av = isd ? avdst : avsrc;
        float acc = 0.f;
        for (int f = 0; f < HIDD; f++) acc += hmat[n * FF + head * HIDD + f] * av[head * HIDD + f];
        if (isd) sAD[n * NHEADS + head] = acc;
        else     sAS[n * NHEADS + head] = acc;
    }
    __syncthreads();
    if (tid < NN * NHEADS) {
        int i = tid / NHEADS, head = tid % NHEADS;
        float sc[NN];
        float mx = -1e30f;
        #pragma unroll
        for (int j = 0; j < NN; j++) {
            float adj = sAdj[i * NN + j];
            float v;
            if (adj > 0.f) {
                float e = sAD[i * NHEADS + head] + sAS[j * NHEADS + head];
                e = (e >= 0.f) ? e : 0.2f * e;
                v = e + logf(adj);
            } else v = -1e30f;
            sc[j] = v;
            mx = fmaxf(mx, v);
        }
        float ssum = 0.f;
        #pragma unroll
        for (int j = 0; j < NN; j++) { float e = expf(sc[j] - mx); sc[j] = e; ssum += e; }
        float inv = 1.f / ssum;
        #pragma unroll
        for (int j = 0; j < NN; j++) sAttn[(i * NN + j) * NHEADS + head] = sc[j] * inv;
    }
    __syncthreads();
}

// ------------------- per-batch graph pipeline -------------------
__global__ void k_stage1(const float* __restrict__ hidden, const int* __restrict__ spans,
                         const float* __restrict__ W1, const float* __restrict__ asrc1,
                         const float* __restrict__ adst1, const float* __restrict__ b1,
                         const float* __restrict__ lng, const float* __restrict__ lnb,
                         const float* __restrict__ W2, const float* __restrict__ asrc2,
                         const float* __restrict__ adst2, const float* __restrict__ b2,
                         const float* __restrict__ dW) {
    int b = blockIdx.x;
    int tid = threadIdx.x;
    __shared__ float sN[NN * HH];
    __shared__ float sH[NN * FF];
    __shared__ float sG[NN * FF];
    __shared__ float sAdj[NN * NN];
    __shared__ float sAS[NN * NHEADS], sAD[NN * NHEADS];
    __shared__ float sAttn[NN * NN * NHEADS];
    __shared__ int sSp[KSP * 2];
    __shared__ float sRed[2];
    __shared__ float sWred[16];

    if (tid < KSP * 2) {
        int k = tid / 2, w = tid % 2;
        sSp[tid] = spans[(b * KSP + k) * 3 + w];
    }
    __syncthreads();

    for (int c = tid; c < HH; c += 256) {
        float g = 0.f;
        #pragma unroll
        for (int p = 0; p < 8; p++) g += d_gfpart[(b * 8 + p) * HH + c];
        sN[c] = g * (1.f / (float)SS);
    }
    for (int k = 0; k < KSP; k++) {
        int st = sSp[k * 2], en = sSp[k * 2 + 1];
        float inv = 1.f / (float)(en - st + 1);
        for (int c = tid; c < HH; c += 256) {
            float a = 0.f;
            for (int s = st; s <= en; s++) a += hidden[((size_t)b * SS + s) * HH + c];
            sN[(1 + k) * HH + c] = a * inv;
        }
    }
    if (tid < NN * NN) {
        int r = tid / NN, c = tid % NN;
        float v = 0.f;
        if (r == c) v += 1.f;
        if (c == 0 && r >= 1) v += 1.f;
        if (r == 0 && c >= 1) v += 1.f;
        if (r >= 1 && c >= 1 && r != c) {
            int i = r - 1, j = c - 1;
            int si = sSp[i * 2], ei = sSp[i * 2 + 1];
            int sj = sSp[j * 2], ej = sSp[j * 2 + 1];
            bool same = (sj == si) && (ej == ei);
            if ((sj <= si) && (ei <= ej) && !same) v += 2.f;
        }
        sAdj[tid] = v;
    }
    __syncthreads();

    {
        float acc[NN];
        #pragma unroll
        for (int n = 0; n < NN; n++) acc[n] = 0.f;
        for (int d = 0; d < HH; d++) {
            float w = W1[d * FF + tid];
            #pragma unroll
            for (int n = 0; n < NN; n++) acc[n] += sN[n * HH + d] * w;
        }
        #pragma unroll
        for (int n = 0; n < NN; n++) sH[n * FF + tid] = acc[n];
    }
    __syncthreads();
    gat_attn(sH, asrc1, adst1, sAdj, sAS, sAD, sAttn, tid);
    {
        int head = tid / HIDD;
        for (int i = 0; i < NN; i++) {
            float acc = b1[tid];
            #pragma unroll
            for (int j = 0; j < NN; j++) acc += sAttn[(i * NN + j) * NHEADS + head] * sH[j * FF + tid];
            sG[i * FF + tid] = fmaxf(acc, 0.f);
        }
    }
    __syncthreads();
    for (int i = 0; i < NN; i++) {
        float v = sG[i * FF + tid];
        float s1 = v, s2 = v * v;
        #pragma unroll
        for (int o = 16; o > 0; o >>= 1) {
            s1 += __shfl_down_sync(0xffffffffu, s1, o);
            s2 += __shfl_down_sync(0xffffffffu, s2, o);
        }
        int wid = tid >> 5, lid = tid & 31;
        if (lid == 0) { sWred[wid] = s1; sWred[8 + wid] = s2; }
        __syncthreads();
        if (tid == 0) {
            float a = 0.f, q = 0.f;
            #pragma unroll
            for (int w = 0; w < 8; w++) { a += sWred[w]; q += sWred[8 + w]; }
            float mu = a / (float)FF;
            float var = q / (float)FF - mu * mu;
            sRed[0] = mu;
            sRed[1] = rsqrtf(var + 1e-5f);
        }
        __syncthreads();
        sG[i * FF + tid] = (v - sRed[0]) * sRed[1] * lng[tid] + lnb[tid];
        __syncthreads();
    }

    {
        float acc[NN];
        #pragma unroll
        for (int n = 0; n < NN; n++) acc[n] = 0.f;
        for (int d = 0; d < FF; d++) {
            float w = W2[d * FF + tid];
            #pragma unroll
            for (int n = 0; n < NN; n++) acc[n] += sG[n * FF + d] * w;
        }
        #pragma unroll
        for (int n = 0; n < NN; n++) sH[n * FF + tid] = acc[n];
    }
    __syncthreads();
    gat_attn(sH, asrc2, adst2, sAdj, sAS, sAD, sAttn, tid);
    {
        int head = tid / HIDD;
        float esum = 0.f;
        for (int i = 0; i < NN; i++) {
            float acc = b2[tid];
            #pragma unroll
            for (int j = 0; j < NN; j++) acc += sAttn[(i * NN + j) * NHEADS + head] * sH[j * FF + tid];
            esum += fmaxf(acc, 0.f);
        }
        float enh = esum * (1.f / (float)NN);
        sG[tid] = enh;
    }
    __syncthreads();
    for (int o = tid; o < OUTD; o += 256) {
        float acc = 0.f;
        for (int c = 0; c < FF; c++) acc += sG[c] * dW[(size_t)(HH + c) * OUTD + o];
        d_eW[b * OUTD + o] = acc;
    }
}

// ------------------- bf16 MMA building blocks -------------------
__device__ __forceinline__ void g2s_fetch(uint4 (&pa)[2], uint4 (&pb)[2],
        const __nv_bfloat16* __restrict__ A, const __nv_bfloat16* __restrict__ B,
        int strA, int strB, int m0, int n0, int kk, int tid) {
    #pragma unroll
    for (int i = 0; i < 2; i++) {
        int lin = tid + i * 256;
        int row = lin >> 2, ch = lin & 3;
        pa[i] = *(const uint4*)(A + (size_t)(m0 + row) * strA + kk + ch * 8);
        pb[i] = *(const uint4*)(B + (size_t)(n0 + row) * strB + kk + ch * 8);
    }
}

__device__ __forceinline__ void s2s_store(uint4 (&pa)[2], uint4 (&pb)[2],
                                          uint4* dA, uint4* dB, int tid) {
    #pragma unroll
    for (int i = 0; i < 2; i++) {
        int lin = tid + i * 256;
        int row = lin >> 2, ch = lin & 3;
        int sw = ch ^ ((row >> 1) & 3);
        dA[row * 4 + sw] = pa[i];
        dB[row * 4 + sw] = pb[i];
    }
}

__device__ __forceinline__ void tile_compute(uint32_t baseA, uint32_t baseB,
                                             int wm0, int wn0, int lane,
                                             float (&acc)[4][4][4]) {
    int rowAo = lane & 15, chAo = lane >> 4;
    int rowBo = (lane & 7) + ((lane & 16) >> 1), chBo = (lane >> 3) & 1;
    #pragma unroll
    for (int ks = 0; ks < 2; ks++) {
        uint32_t a[4][4], b[2][4];
        #pragma unroll
        for (int mi = 0; mi < 4; mi++) {
            int row = wm0 + mi * 16 + rowAo;
            int ch = ks * 2 + chAo;
            uint32_t addr = baseA + row * 64 + ((ch ^ ((row >> 1) & 3)) << 4);
            asm volatile("ldmatrix.sync.aligned.m8n8.x4.shared.b16 {%0,%1,%2,%3}, [%4];"
                : "=r"(a[mi][0]), "=r"(a[mi][1]), "=r"(a[mi][2]), "=r"(a[mi][3]) : "r"(addr));
        }
        #pragma unroll
        for (int ng = 0; ng < 2; ng++) {
            int row = wn0 + ng * 16 + rowBo;
            int ch = ks * 2 + chBo;
            uint32_t addr = baseB + row * 64 + ((ch ^ ((row >> 1) & 3)) << 4);
            asm volatile("ldmatrix.sync.aligned.m8n8.x4.shared.b16 {%0,%1,%2,%3}, [%4];"
                : "=r"(b[ng][0]), "=r"(b[ng][1]), "=r"(b[ng][2]), "=r"(b[ng][3]) : "r"(addr));
        }
        #pragma unroll
        for (int mi = 0; mi < 4; mi++)
            #pragma unroll
            for (int ni = 0; ni < 4; ni++) {
                uint32_t b0 = b[ni >> 1][(ni & 1) * 2 + 0];
                uint32_t b1 = b[ni >> 1][(ni & 1) * 2 + 1];
                asm volatile("mma.sync.aligned.m16n8k16.row.col.f32.bf16.bf16.f32 "
                    "{%0,%1,%2,%3}, {%4,%5,%6,%7}, {%8,%9}, {%0,%1,%2,%3};"
                    : "+f"(acc[mi][ni][0]), "+f"(acc[mi][ni][1]),
                      "+f"(acc[mi][ni][2]), "+f"(acc[mi][ni][3])
                    : "r"(a[mi][0]), "r"(a[mi][1]), "r"(a[mi][2]), "r"(a[mi][3]),
                      "r"(b0), "r"(b1));
            }
    }
}

// ------------------- GEMM1: Y = hidden_bf @ W_bf^T + cover*eW + db -------------------
__global__ void __launch_bounds__(256, 2) k_gemm1_mma(const float* __restrict__ db) {
    __shared__ uint4 sA[2][512], sB[2][512];
    int tid = threadIdx.x, lane = tid & 31, wid = tid >> 5;
    int m0 = blockIdx.y * 128, n0 = blockIdx.x * 128;
    int wm0 = (wid & 1) * 64, wn0 = (wid >> 1) * 32;
    float acc[4][4][4] = {};
    uint4 pa[2], pb[2];
    g2s_fetch(pa, pb, d_hidbf, d_wbf, HH, HH, m0, n0, 0, tid);
    s2s_store(pa, pb, sA[0], sB[0], tid);
    __syncthreads();
    const int NT = HH / 32;
    for (int it = 0; it < NT; ++it) {
        if (it + 1 < NT) g2s_fetch(pa, pb, d_hidbf, d_wbf, HH, HH, m0, n0, (it + 1) * 32, tid);
        tile_compute(smem_u32(sA[it & 1]), smem_u32(sB[it & 1]), wm0, wn0, lane, acc);
        if (it + 1 < NT) s2s_store(pa, pb, sA[(it + 1) & 1], sB[(it + 1) & 1], tid);
        __syncthreads();
    }
    int g = lane >> 2, tq = lane & 3;
    #pragma unroll
    for (int mi = 0; mi < 4; mi++) {
        #pragma unroll
        for (int half = 0; half < 2; half++) {
            int r = m0 + wm0 + mi * 16 + g + half * 8;
            int b = r >> 10;
            float cov = d_cover[r];
            #pragma unroll
            for (int ni = 0; ni < 4; ni++) {
                int c = n0 + wn0 + ni * 8 + tq * 2;
                float2 ew = *(const float2*)&d_eW[b * OUTD + c];
                float2 dbv = *(const float2*)&db[c];
                float2 res;
                res.x = acc[mi][ni][half * 2 + 0] + cov * ew.x + dbv.x;
                res.y = acc[mi][ni][half * 2 + 1] + cov * ew.y + dbv.y;
                *(float2*)&d_Y[(size_t)r * OUTD + c] = res;
            }
        }
    }
}

// ------------------- RoPE + extended operand build (bf16 out) -------------------
__global__ void k_build(const int* __restrict__ spans, const float* __restrict__ gc,
                        const float* __restrict__ gs, const float* __restrict__ gw,
                        const float* __restrict__ corr) {
    int idx = blockIdx.x * 256 + threadIdx.x;   // (b*T+t)*S + s
    int s = idx & (SS - 1);
    int t = (idx >> 10) & (TT - 1);
    int b = idx >> 13;
    const float* y = d_Y + ((size_t)(b << 10) + s) * OUTD + t * (2 * DDI);
    __nv_bfloat162* qo = (__nv_bfloat162*)(d_qext + (size_t)idx * KEP);
    __nv_bfloat162* ko = (__nv_bfloat162*)(d_kext + (size_t)idx * KEP);
    const float L2C = 0.41524101186092573f;
    float sf = (float)s;
    #pragma unroll
    for (int i = 0; i < DDI / 2; i++) {
        float inv = exp2f(-(float)i * L2C);
        float ang = sf * inv;
        float sv, cv;
        sincosf(ang, &sv, &cv);
        float2 q = *(const float2*)&y[2 * i];
        float2 k = *(const float2*)&y[DDI + 2 * i];
        qo[i] = __floats2bfloat162_rn(q.x * cv - q.y * sv, q.y * cv + q.x * sv);
        ko[i] = __floats2bfloat162_rn(k.x * cv - k.y * sv, k.y * cv + k.x * sv);
    }
    const int* sp = spans + b * KSP * 3;
    float g0w = gw[0], g1w = gw[1];
    float g0c = gc[0], g1c = gc[1];
    float g0si = 1.f / gs[0], g1si = 1.f / gs[1];
    #pragma unroll
    for (int kk = 0; kk < KSP; kk++) {
        int st = sp[kk * 3], en = sp[kk * 3 + 1], et = sp[kk * 3 + 2];
        float ct = corr[et * TT + t];
        float d0 = (sf - (float)st - g0c) * g0si;
        float d1 = (sf - (float)st - g1c) * g1si;
        float e0 = (sf - (float)en - g0c) * g0si;
        float e1 = (sf - (float)en - g1c) * g1si;
        qo[32 + kk] = __floats2bfloat162_rn(ct * g0w * expf(-0.5f * d0 * d0),
                                            ct * g1w * expf(-0.5f * d1 * d1));
        ko[32 + kk] = __floats2bfloat162_rn(g0w * expf(-0.5f * e0 * e0),
                                            g1w * expf(-0.5f * e1 * e1));
    }
    __nv_bfloat162 z = __floats2bfloat162_rn(0.f, 0.f);
    #pragma unroll
    for (int i = 40; i < 48; i++) { qo[i] = z; ko[i] = z; }
}

// ------------------- GEMM2: logits (batched 1024x1024x96) + mask epilogue -------------------
__global__ void __launch_bounds__(256, 2) k_gemm2_mma(const float* __restrict__ mask,
                                                      float* __restrict__ out) {
    __shared__ uint4 sA[2][512], sB[2][512];
    int bt = blockIdx.z;
    int b = bt >> 3;
    const __nv_bfloat16* Ab = d_qext + (size_t)bt * SS * KEP;
    const __nv_bfloat16* Bb = d_kext + (size_t)bt * SS * KEP;
    int tid = threadIdx.x, lane = tid & 31, wid = tid >> 5;
    int m0 = blockIdx.y * 128, n0 = blockIdx.x * 128;
    int wm0 = (wid & 1) * 64, wn0 = (wid >> 1) * 32;
    float acc[4][4][4] = {};
    uint4 pa[2], pb[2];
    g2s_fetch(pa, pb, Ab, Bb, KEP, KEP, m0, n0, 0, tid);
    s2s_store(pa, pb, sA[0], sB[0], tid);
    __syncthreads();
    const int NT = KEP / 32;
    for (int it = 0; it < NT; ++it) {
        if (it + 1 < NT) g2s_fetch(pa, pb, Ab, Bb, KEP, KEP, m0, n0, (it + 1) * 32, tid);
        tile_compute(smem_u32(sA[it & 1]), smem_u32(sB[it & 1]), wm0, wn0, lane, acc);
        if (it + 1 < NT) s2s_store(pa, pb, sA[(it + 1) & 1], sB[(it + 1) & 1], tid);
        __syncthreads();
    }
    int g = lane >> 2, tq = lane & 3;
    #pragma unroll
    for (int mi = 0; mi < 4; mi++) {
        #pragma unroll
        for (int half = 0; half < 2; half++) {
            int m = m0 + wm0 + mi * 16 + g + half * 8;
            #pragma unroll
            for (int ni = 0; ni < 4; ni++) {
                int n = n0 + wn0 + ni * 8 + tq * 2;
                float2 pd = *(const float2*)&mask[b * SS + n];
                float v0 = acc[mi][ni][half * 2 + 0] * pd.x - (1.f - pd.x) * NEGC;
                float v1 = acc[mi][ni][half * 2 + 1] * pd.y - (1.f - pd.y) * NEGC;
                if (m > n)     v0 -= NEGC;
                if (m > n + 1) v1 -= NEGC;
                float2 res;
                res.x = v0 * 0.125f;
                res.y = v1 * 0.125f;
                *(float2*)&out[((size_t)bt * SS + m) * SS + n] = res;
            }
        }
    }
}

// ------------------- launch -------------------
extern "C" void kernel_launch(void* const* d_in, const int* in_sizes, int n_in,
                              void* d_out, int out_size) {
    const float* hidden = (const float*)d_in[0];
    const float* amask  = (const float*)d_in[1];
    const int*   spans  = (const int*)d_in[2];
    const float* W1     = (const float*)d_in[3];
    const float* asrc1  = (const float*)d_in[4];
    const float* adst1  = (const float*)d_in[5];
    const float* b1     = (const float*)d_in[6];
    const float* lng    = (const float*)d_in[7];
    const float* lnb    = (const float*)d_in[8];
    const float* W2     = (const float*)d_in[9];
    const float* asrc2  = (const float*)d_in[10];
    const float* adst2  = (const float*)d_in[11];
    const float* b2     = (const float*)d_in[12];
    const float* dW     = (const float*)d_in[13];
    const float* db     = (const float*)d_in[14];
    const float* gc     = (const float*)d_in[15];
    const float* gsg    = (const float*)d_in[16];
    const float* gwt    = (const float*)d_in[17];
    const float* corr   = (const float*)d_in[18];
    float* out = (float*)d_out;

    k_cvthid<<<(BB * SS * HH) / 1024, 256>>>(hidden);
    k_cvtW<<<dim3(OUTD / 32, HH / 32), dim3(32, 8)>>>(dW);
    k_gfpart<<<dim3(8, BB), 256>>>(hidden);
    k_cover<<<(BB * SS + 255) / 256, 256>>>(spans);
    k_stage1<<<BB, 256>>>(hidden, spans, W1, asrc1, adst1, b1, lng, lnb,
                          W2, asrc2, adst2, b2, dW);
    k_gemm1_mma<<<dim3(OUTD / 128, (BB * SS) / 128), 256>>>(db);
    k_build<<<(BB * TT * SS) / 256, 256>>>(spans, gc, gsg, gwt, corr);
    k_gemm2_mma<<<dim3(SS / 128, SS / 128, BB * TT), 256>>>(amask, out);
}

// round 5
// speedup vs baseline: 2.4277x; 1.0964x over previous
#include <cuda_runtime.h>
#include <cuda_bf16.h>
#include <math.h>
#include <cstdint>
#include <cstddef>

#define BB 8
#define SS 1024
#define HH 768
#define TT 8
#define DDI 64
#define HIDD 128
#define KSP 8
#define NHEADS 2
#define NN 9
#define FF 256      // NHEADS*HIDD
#define OUTD 1024   // TT*2*DDI
#define KEP 96      // 64 rope + 16 gaussian + 16 zero pad
#define NEGC 1000000000000.0f
#define L2C 0.41524101186092573f   // log2(10000)/32

// ------------------- device scratch -------------------
__device__ float d_gfpart[BB * 8 * HH];
__device__ float d_eW[BB * OUTD];
__device__ float d_cover[BB * SS];
__device__ __nv_bfloat16 d_hidbf[(size_t)BB * SS * HH];
__device__ __nv_bfloat16 d_wbf[(size_t)OUTD * HH];               // W^T bf16 [n][k]
__device__ __nv_bfloat16 d_qext[(size_t)BB * TT * SS * KEP];
__device__ __nv_bfloat16 d_kext[(size_t)BB * TT * SS * KEP];

__device__ __forceinline__ uint32_t smem_u32(const void* p) {
    uint32_t a;
    asm("{ .reg .u64 t; cvta.to.shared.u64 t, %1; cvt.u32.u64 %0, t; }" : "=r"(a) : "l"(p));
    return a;
}

// ------------------- conversion kernels -------------------
__global__ void k_cvthid(const float* __restrict__ h) {
    int i = (blockIdx.x * 256 + threadIdx.x) * 4;
    float4 v = *(const float4*)&h[i];
    __nv_bfloat162* o = (__nv_bfloat162*)&d_hidbf[i];
    o[0] = __floats2bfloat162_rn(v.x, v.y);
    o[1] = __floats2bfloat162_rn(v.z, v.w);
}

__global__ void k_cvtW(const float* __restrict__ W) {   // (768,1024) -> bf16 [1024][768]
    __shared__ float t[32][33];
    int k0 = blockIdx.y * 32, n0 = blockIdx.x * 32;
    int tx = threadIdx.x, ty = threadIdx.y;
    #pragma unroll
    for (int i = 0; i < 32; i += 8)
        t[ty + i][tx] = W[(size_t)(k0 + ty + i) * OUTD + n0 + tx];
    __syncthreads();
    #pragma unroll
    for (int i = 0; i < 32; i += 8)
        d_wbf[(size_t)(n0 + ty + i) * HH + k0 + tx] = __float2bfloat16(t[tx][ty + i]);
}

// ------------------- partial sums for global_feat -------------------
__global__ void k_gfpart(const float* __restrict__ hidden) {
    int b = blockIdx.y, p = blockIdx.x;
    for (int c = threadIdx.x; c < HH; c += 256) {
        float acc = 0.f;
        const float* base = hidden + ((size_t)b * SS + (size_t)p * 128) * HH + c;
        #pragma unroll 4
        for (int s = 0; s < 128; s++) acc += base[(size_t)s * HH];
        d_gfpart[(b * 8 + p) * HH + c] = acc;
    }
}

// ------------------- cover counts -------------------
__global__ void k_cover(const int* __restrict__ spans) {
    int idx = blockIdx.x * 256 + threadIdx.x;
    if (idx >= BB * SS) return;
    int b = idx >> 10, s = idx & (SS - 1);
    const int* sp = spans + b * KSP * 3;
    float c = 0.f;
    #pragma unroll
    for (int k = 0; k < KSP; k++) {
        int st = sp[k * 3], en = sp[k * 3 + 1];
        c += (s >= st && s <= en) ? 1.f : 0.f;
    }
    d_cover[idx] = c;
}

// ------------------- GAT attention helper -------------------
__device__ __forceinline__ void gat_attn(const float* __restrict__ hmat,
                                         const float* __restrict__ avsrc,
                                         const float* __restrict__ avdst,
                                         const float* __restrict__ sAdj,
                                         float* sAS, float* sAD, float* sAttn, int tid) {
    if (tid < NN * NHEADS * 2) {
        int n = tid / (NHEADS * 2);
        int rem = tid % (NHEADS * 2);
        int head = rem % NHEADS;
        int isd = rem / NHEADS;
        const float* av = isd ? avdst : avsrc;
        float acc = 0.f;
        for (int f = 0; f < HIDD; f++) acc += hmat[n * FF + head * HIDD + f] * av[head * HIDD + f];
        if (isd) sAD[n * NHEADS + head] = acc;
        else     sAS[n * NHEADS + head] = acc;
    }
    __syncthreads();
    if (tid < NN * NHEADS) {
        int i = tid / NHEADS, head = tid % NHEADS;
        float sc[NN];
        float mx = -1e30f;
        #pragma unroll
        for (int j = 0; j < NN; j++) {
            float adj = sAdj[i * NN + j];
            float v;
            if (adj > 0.f) {
                float e = sAD[i * NHEADS + head] + sAS[j * NHEADS + head];
                e = (e >= 0.f) ? e : 0.2f * e;
                v = e + logf(adj);
            } else v = -1e30f;
            sc[j] = v;
            mx = fmaxf(mx, v);
        }
        float ssum = 0.f;
        #pragma unroll
        for (int j = 0; j < NN; j++) { float e = expf(sc[j] - mx); sc[j] = e; ssum += e; }
        float inv = 1.f / ssum;
        #pragma unroll
        for (int j = 0; j < NN; j++) sAttn[(i * NN + j) * NHEADS + head] = sc[j] * inv;
    }
    __syncthreads();
}

// ------------------- per-batch graph pipeline -------------------
__global__ void k_stage1(const float* __restrict__ hidden, const int* __restrict__ spans,
                         const float* __restrict__ W1, const float* __restrict__ asrc1,
                         const float* __restrict__ adst1, const float* __restrict__ b1,
                         const float* __restrict__ lng, const float* __restrict__ lnb,
                         const float* __restrict__ W2, const float* __restrict__ asrc2,
                         const float* __restrict__ adst2, const float* __restrict__ b2,
                         const float* __restrict__ dW) {
    int b = blockIdx.x;
    int tid = threadIdx.x;
    __shared__ float sN[NN * HH];
    __shared__ float sH[NN * FF];
    __shared__ float sG[NN * FF];
    __shared__ float sAdj[NN * NN];
    __shared__ float sAS[NN * NHEADS], sAD[NN * NHEADS];
    __shared__ float sAttn[NN * NN * NHEADS];
    __shared__ int sSp[KSP * 2];
    __shared__ float sRed[2];
    __shared__ float sWred[16];

    if (tid < KSP * 2) {
        int k = tid / 2, w = tid % 2;
        sSp[tid] = spans[(b * KSP + k) * 3 + w];
    }
    __syncthreads();

    for (int c = tid; c < HH; c += 256) {
        float g = 0.f;
        #pragma unroll
        for (int p = 0; p < 8; p++) g += d_gfpart[(b * 8 + p) * HH + c];
        sN[c] = g * (1.f / (float)SS);
    }
    for (int k = 0; k < KSP; k++) {
        int st = sSp[k * 2], en = sSp[k * 2 + 1];
        float inv = 1.f / (float)(en - st + 1);
        for (int c = tid; c < HH; c += 256) {
            float a = 0.f;
            for (int s = st; s <= en; s++) a += hidden[((size_t)b * SS + s) * HH + c];
            sN[(1 + k) * HH + c] = a * inv;
        }
    }
    if (tid < NN * NN) {
        int r = tid / NN, c = tid % NN;
        float v = 0.f;
        if (r == c) v += 1.f;
        if (c == 0 && r >= 1) v += 1.f;
        if (r == 0 && c >= 1) v += 1.f;
        if (r >= 1 && c >= 1 && r != c) {
            int i = r - 1, j = c - 1;
            int si = sSp[i * 2], ei = sSp[i * 2 + 1];
            int sj = sSp[j * 2], ej = sSp[j * 2 + 1];
            bool same = (sj == si) && (ej == ei);
            if ((sj <= si) && (ei <= ej) && !same) v += 2.f;
        }
        sAdj[tid] = v;
    }
    __syncthreads();

    {
        float acc[NN];
        #pragma unroll
        for (int n = 0; n < NN; n++) acc[n] = 0.f;
        for (int d = 0; d < HH; d++) {
            float w = W1[d * FF + tid];
            #pragma unroll
            for (int n = 0; n < NN; n++) acc[n] += sN[n * HH + d] * w;
        }
        #pragma unroll
        for (int n = 0; n < NN; n++) sH[n * FF + tid] = acc[n];
    }
    __syncthreads();
    gat_attn(sH, asrc1, adst1, sAdj, sAS, sAD, sAttn, tid);
    {
        int head = tid / HIDD;
        for (int i = 0; i < NN; i++) {
            float acc = b1[tid];
            #pragma unroll
            for (int j = 0; j < NN; j++) acc += sAttn[(i * NN + j) * NHEADS + head] * sH[j * FF + tid];
            sG[i * FF + tid] = fmaxf(acc, 0.f);
        }
    }
    __syncthreads();
    for (int i = 0; i < NN; i++) {
        float v = sG[i * FF + tid];
        float s1 = v, s2 = v * v;
        #pragma unroll
        for (int o = 16; o > 0; o >>= 1) {
            s1 += __shfl_down_sync(0xffffffffu, s1, o);
            s2 += __shfl_down_sync(0xffffffffu, s2, o);
        }
        int wid = tid >> 5, lid = tid & 31;
        if (lid == 0) { sWred[wid] = s1; sWred[8 + wid] = s2; }
        __syncthreads();
        if (tid == 0) {
            float a = 0.f, q = 0.f;
            #pragma unroll
            for (int w = 0; w < 8; w++) { a += sWred[w]; q += sWred[8 + w]; }
            float mu = a / (float)FF;
            float var = q / (float)FF - mu * mu;
            sRed[0] = mu;
            sRed[1] = rsqrtf(var + 1e-5f);
        }
        __syncthreads();
        sG[i * FF + tid] = (v - sRed[0]) * sRed[1] * lng[tid] + lnb[tid];
        __syncthreads();
    }

    {
        float acc[NN];
        #pragma unroll
        for (int n = 0; n < NN; n++) acc[n] = 0.f;
        for (int d = 0; d < FF; d++) {
            float w = W2[d * FF + tid];
            #pragma unroll
            for (int n = 0; n < NN; n++) acc[n] += sG[n * FF + d] * w;
        }
        #pragma unroll
        for (int n = 0; n < NN; n++) sH[n * FF + tid] = acc[n];
    }
    __syncthreads();
    gat_attn(sH, asrc2, adst2, sAdj, sAS, sAD, sAttn, tid);
    {
        int head = tid / HIDD;
        float esum = 0.f;
        for (int i = 0; i < NN; i++) {
            float acc = b2[tid];
            #pragma unroll
            for (int j = 0; j < NN; j++) acc += sAttn[(i * NN + j) * NHEADS + head] * sH[j * FF + tid];
            esum += fmaxf(acc, 0.f);
        }
        float enh = esum * (1.f / (float)NN);
        sG[tid] = enh;
    }
    __syncthreads();
    for (int o = tid; o < OUTD; o += 256) {
        float acc = 0.f;
        for (int c = 0; c < FF; c++) acc += sG[c] * dW[(size_t)(HH + c) * OUTD + o];
        d_eW[b * OUTD + o] = acc;
    }
}

// ------------------- bf16 MMA building blocks -------------------
__device__ __forceinline__ void g2s_fetch(uint4 (&pa)[2], uint4 (&pb)[2],
        const __nv_bfloat16* __restrict__ A, const __nv_bfloat16* __restrict__ B,
        int strA, int strB, int m0, int n0, int kk, int tid) {
    #pragma unroll
    for (int i = 0; i < 2; i++) {
        int lin = tid + i * 256;
        int row = lin >> 2, ch = lin & 3;
        pa[i] = *(const uint4*)(A + (size_t)(m0 + row) * strA + kk + ch * 8);
        pb[i] = *(const uint4*)(B + (size_t)(n0 + row) * strB + kk + ch * 8);
    }
}

__device__ __forceinline__ void s2s_store(uint4 (&pa)[2], uint4 (&pb)[2],
                                          uint4* dA, uint4* dB, int tid) {
    #pragma unroll
    for (int i = 0; i < 2; i++) {
        int lin = tid + i * 256;
        int row = lin >> 2, ch = lin & 3;
        int sw = ch ^ ((row >> 1) & 3);
        dA[row * 4 + sw] = pa[i];
        dB[row * 4 + sw] = pb[i];
    }
}

__device__ __forceinline__ void tile_compute(uint32_t baseA, uint32_t baseB,
                                             int wm0, int wn0, int lane,
                                             float (&acc)[4][4][4]) {
    int rowAo = lane & 15, chAo = lane >> 4;
    int rowBo = (lane & 7) + ((lane & 16) >> 1), chBo = (lane >> 3) & 1;
    #pragma unroll
    for (int ks = 0; ks < 2; ks++) {
        uint32_t a[4][4], b[2][4];
        #pragma unroll
        for (int mi = 0; mi < 4; mi++) {
            int row = wm0 + mi * 16 + rowAo;
            int ch = ks * 2 + chAo;
            uint32_t addr = baseA + row * 64 + ((ch ^ ((row >> 1) & 3)) << 4);
            asm volatile("ldmatrix.sync.aligned.m8n8.x4.shared.b16 {%0,%1,%2,%3}, [%4];"
                : "=r"(a[mi][0]), "=r"(a[mi][1]), "=r"(a[mi][2]), "=r"(a[mi][3]) : "r"(addr));
        }
        #pragma unroll
        for (int ng = 0; ng < 2; ng++) {
            int row = wn0 + ng * 16 + rowBo;
            int ch = ks * 2 + chBo;
            uint32_t addr = baseB + row * 64 + ((ch ^ ((row >> 1) & 3)) << 4);
            asm volatile("ldmatrix.sync.aligned.m8n8.x4.shared.b16 {%0,%1,%2,%3}, [%4];"
                : "=r"(b[ng][0]), "=r"(b[ng][1]), "=r"(b[ng][2]), "=r"(b[ng][3]) : "r"(addr));
        }
        #pragma unroll
        for (int mi = 0; mi < 4; mi++)
            #pragma unroll
            for (int ni = 0; ni < 4; ni++) {
                uint32_t b0 = b[ni >> 1][(ni & 1) * 2 + 0];
                uint32_t b1 = b[ni >> 1][(ni & 1) * 2 + 1];
                asm volatile("mma.sync.aligned.m16n8k16.row.col.f32.bf16.bf16.f32 "
                    "{%0,%1,%2,%3}, {%4,%5,%6,%7}, {%8,%9}, {%0,%1,%2,%3};"
                    : "+f"(acc[mi][ni][0]), "+f"(acc[mi][ni][1]),
                      "+f"(acc[mi][ni][2]), "+f"(acc[mi][ni][3])
                    : "r"(a[mi][0]), "r"(a[mi][1]), "r"(a[mi][2]), "r"(a[mi][3]),
                      "r"(b0), "r"(b1));
            }
    }
}

// ------------- GEMM1 fused: Y = hid@W^T + cover*eW + db, then RoPE -> q/k bf16 -------------
__global__ void __launch_bounds__(256, 2) k_gemm1_mma(const float* __restrict__ db) {
    __shared__ uint4 sA[2][512], sB[2][512];
    int tid = threadIdx.x, lane = tid & 31, wid = tid >> 5;
    int m0 = blockIdx.y * 128, n0 = blockIdx.x * 128;
    int wm0 = (wid & 1) * 64, wn0 = (wid >> 1) * 32;
    float acc[4][4][4] = {};
    uint4 pa[2], pb[2];
    g2s_fetch(pa, pb, d_hidbf, d_wbf, HH, HH, m0, n0, 0, tid);
    s2s_store(pa, pb, sA[0], sB[0], tid);
    __syncthreads();
    const int NT = HH / 32;
    for (int it = 0; it < NT; ++it) {
        if (it + 1 < NT) g2s_fetch(pa, pb, d_hidbf, d_wbf, HH, HH, m0, n0, (it + 1) * 32, tid);
        tile_compute(smem_u32(sA[it & 1]), smem_u32(sB[it & 1]), wm0, wn0, lane, acc);
        if (it + 1 < NT) s2s_store(pa, pb, sA[(it + 1) & 1], sB[(it + 1) & 1], tid);
        __syncthreads();
    }
    int g = lane >> 2, tq = lane & 3;
    int t = n0 >> 7;   // 128-col tile == one t slice
    #pragma unroll
    for (int mi = 0; mi < 4; mi++) {
        #pragma unroll
        for (int half = 0; half < 2; half++) {
            int r = m0 + wm0 + mi * 16 + g + half * 8;
            int b = r >> 10, s = r & (SS - 1);
            float cov = d_cover[r];
            float sf = (float)s;
            size_t rowbase = ((size_t)(b * TT + t) * SS + s) * KEP;
            #pragma unroll
            for (int ni = 0; ni < 4; ni++) {
                int jj = wn0 + ni * 8 + tq * 2;   // even, 0..126
                int c = n0 + jj;
                float2 ew = *(const float2*)&d_eW[b * OUTD + c];
                float2 dbv = *(const float2*)&db[c];
                float x = acc[mi][ni][half * 2 + 0] + cov * ew.x + dbv.x;
                float y = acc[mi][ni][half * 2 + 1] + cov * ew.y + dbv.y;
                int i = (jj & 63) >> 1;
                float ang = sf * exp2f(-(float)i * L2C);
                float sv, cvv;
                sincosf(ang, &sv, &cvv);
                __nv_bfloat162 v = __floats2bfloat162_rn(x * cvv - y * sv, y * cvv + x * sv);
                __nv_bfloat16* dst = ((jj < 64) ? d_qext : d_kext) + rowbase + (jj & 63);
                *(__nv_bfloat162*)dst = v;
            }
        }
    }
}

// ------------------- gaussian extras (cols 64..95 of q/k ext) -------------------
__global__ void k_fillext(const int* __restrict__ spans, const float* __restrict__ gc,
                          const float* __restrict__ gs, const float* __restrict__ gw,
                          const float* __restrict__ corr) {
    int idx = blockIdx.x * 256 + threadIdx.x;   // (b*T+t)*S + s
    int s = idx & (SS - 1);
    int t = (idx >> 10) & (TT - 1);
    int b = idx >> 13;
    __nv_bfloat162* qo = (__nv_bfloat162*)(d_qext + (size_t)idx * KEP);
    __nv_bfloat162* ko = (__nv_bfloat162*)(d_kext + (size_t)idx * KEP);
    float sf = (float)s;
    const int* sp = spans + b * KSP * 3;
    float g0w = gw[0], g1w = gw[1];
    float g0c = gc[0], g1c = gc[1];
    float g0si = 1.f / gs[0], g1si = 1.f / gs[1];
    #pragma unroll
    for (int kk = 0; kk < KSP; kk++) {
        int st = sp[kk * 3], en = sp[kk * 3 + 1], et = sp[kk * 3 + 2];
        float ct = corr[et * TT + t];
        float d0 = (sf - (float)st - g0c) * g0si;
        float d1 = (sf - (float)st - g1c) * g1si;
        float e0 = (sf - (float)en - g0c) * g0si;
        float e1 = (sf - (float)en - g1c) * g1si;
        qo[32 + kk] = __floats2bfloat162_rn(ct * g0w * expf(-0.5f * d0 * d0),
                                            ct * g1w * expf(-0.5f * d1 * d1));
        ko[32 + kk] = __floats2bfloat162_rn(g0w * expf(-0.5f * e0 * e0),
                                            g1w * expf(-0.5f * e1 * e1));
    }
    __nv_bfloat162 z = __floats2bfloat162_rn(0.f, 0.f);
    #pragma unroll
    for (int i = 40; i < 48; i++) { qo[i] = z; ko[i] = z; }
}

// ------------- GEMM2: logits (batched 1024x1024x96) + mask epilogue + tril skip -------------
__global__ void __launch_bounds__(256, 2) k_gemm2_mma(const float* __restrict__ mask,
                                                      float* __restrict__ out) {
    __shared__ uint4 sA[2][512], sB[2][512];
    int bt = blockIdx.z;
    int b = bt >> 3;
    int tid = threadIdx.x;
    int m0 = blockIdx.y * 128, n0 = blockIdx.x * 128;

    if (m0 > n0) {
        // fully below the diagonal: logits contribution (|v|<~1e3) is negligible vs -1e12
        int colq = (tid & 31) * 4;
        float4 pd = *(const float4*)&mask[b * SS + n0 + colq];
        float4 v;
        v.x = (-(1.f - pd.x) * NEGC - NEGC) * 0.125f;
        v.y = (-(1.f - pd.y) * NEGC - NEGC) * 0.125f;
        v.z = (-(1.f - pd.z) * NEGC - NEGC) * 0.125f;
        v.w = (-(1.f - pd.w) * NEGC - NEGC) * 0.125f;
        int r0 = tid >> 5;
        #pragma unroll
        for (int p = 0; p < 16; p++) {
            int m = m0 + p * 8 + r0;
            *(float4*)&out[((size_t)bt * SS + m) * SS + n0 + colq] = v;
        }
        return;
    }

    const __nv_bfloat16* Ab = d_qext + (size_t)bt * SS * KEP;
    const __nv_bfloat16* Bb = d_kext + (size_t)bt * SS * KEP;
    int lane = tid & 31, wid = tid >> 5;
    int wm0 = (wid & 1) * 64, wn0 = (wid >> 1) * 32;
    float acc[4][4][4] = {};
    uint4 pa[2], pb[2];
    g2s_fetch(pa, pb, Ab, Bb, KEP, KEP, m0, n0, 0, tid);
    s2s_store(pa, pb, sA[0], sB[0], tid);
    __syncthreads();
    const int NT = KEP / 32;
    for (int it = 0; it < NT; ++it) {
        if (it + 1 < NT) g2s_fetch(pa, pb, Ab, Bb, KEP, KEP, m0, n0, (it + 1) * 32, tid);
        tile_compute(smem_u32(sA[it & 1]), smem_u32(sB[it & 1]), wm0, wn0, lane, acc);
        if (it + 1 < NT) s2s_store(pa, pb, sA[(it + 1) & 1], sB[(it + 1) & 1], tid);
        __syncthreads();
    }
    int g = lane >> 2, tq = lane & 3;
    #pragma unroll
    for (int mi = 0; mi < 4; mi++) {
        #pragma unroll
        for (int half = 0; half < 2; half++) {
            int m = m0 + wm0 + mi * 16 + g + half * 8;
            #pragma unroll
            for (int ni = 0; ni < 4; ni++) {
                int n = n0 + wn0 + ni * 8 + tq * 2;
                float2 pd = *(const float2*)&mask[b * SS + n];
                float v0 = acc[mi][ni][half * 2 + 0] * pd.x - (1.f - pd.x) * NEGC;
                float v1 = acc[mi][ni][half * 2 + 1] * pd.y - (1.f - pd.y) * NEGC;
                if (m > n)     v0 -= NEGC;
                if (m > n + 1) v1 -= NEGC;
                float2 res;
                res.x = v0 * 0.125f;
                res.y = v1 * 0.125f;
                *(float2*)&out[((size_t)bt * SS + m) * SS + n] = res;
            }
        }
    }
}

// ------------------- launch -------------------
extern "C" void kernel_launch(void* const* d_in, const int* in_sizes, int n_in,
                              void* d_out, int out_size) {
    const float* hidden = (const float*)d_in[0];
    const float* amask  = (const float*)d_in[1];
    const int*   spans  = (const int*)d_in[2];
    const float* W1     = (const float*)d_in[3];
    const float* asrc1  = (const float*)d_in[4];
    const float* adst1  = (const float*)d_in[5];
    const float* b1     = (const float*)d_in[6];
    const float* lng    = (const float*)d_in[7];
    const float* lnb    = (const float*)d_in[8];
    const float* W2     = (const float*)d_in[9];
    const float* asrc2  = (const float*)d_in[10];
    const float* adst2  = (const float*)d_in[11];
    const float* b2     = (const float*)d_in[12];
    const float* dW     = (const float*)d_in[13];
    const float* db     = (const float*)d_in[14];
    const float* gc     = (const float*)d_in[15];
    const float* gsg    = (const float*)d_in[16];
    const float* gwt    = (const float*)d_in[17];
    const float* corr   = (const float*)d_in[18];
    float* out = (float*)d_out;

    k_cvthid<<<(BB * SS * HH) / 1024, 256>>>(hidden);
    k_cvtW<<<dim3(OUTD / 32, HH / 32), dim3(32, 8)>>>(dW);
    k_gfpart<<<dim3(8, BB), 256>>>(hidden);
    k_cover<<<(BB * SS + 255) / 256, 256>>>(spans);
    k_stage1<<<BB, 256>>>(hidden, spans, W1, asrc1, adst1, b1, lng, lnb,
                          W2, asrc2, adst2, b2, dW);
    k_gemm1_mma<<<dim3(OUTD / 128, (BB * SS) / 128), 256>>>(db);
    k_fillext<<<(BB * TT * SS) / 256, 256>>>(spans, gc, gsg, gwt, corr);
    k_gemm2_mma<<<dim3(SS / 128, SS / 128, BB * TT), 256>>>(amask, out);
}

// round 6
// speedup vs baseline: 2.6548x; 1.0936x over previous
#include <cuda_runtime.h>
#include <cuda_bf16.h>
#include <math.h>
#include <cstdint>
#include <cstddef>

#define BB 8
#define SS 1024
#define HH 768
#define TT 8
#define DDI 64
#define HIDD 128
#define KSP 8
#define NHEADS 2
#define NN 9
#define FF 256      // NHEADS*HIDD
#define OUTD 1024   // TT*2*DDI
#define KEP 96      // 64 rope + 16 gaussian + 16 zero pad
#define NEGC 1000000000000.0f
#define L2C 0.41524101186092573f   // log2(10000)/32

// ------------------- device scratch -------------------
__device__ float d_gfpart[BB * 8 * HH];
__device__ float d_enh[BB * FF];
__device__ float d_eW[BB * OUTD];
__device__ float d_cover[BB * SS];
__device__ __nv_bfloat16 d_hidbf[(size_t)BB * SS * HH];
__device__ __nv_bfloat16 d_wbf[(size_t)OUTD * HH];               // W^T bf16 [n][k]
__device__ __nv_bfloat16 d_qext[(size_t)BB * TT * SS * KEP];
__device__ __nv_bfloat16 d_kext[(size_t)BB * TT * SS * KEP];

__device__ __forceinline__ uint32_t smem_u32(const void* p) {
    uint32_t a;
    asm("{ .reg .u64 t; cvta.to.shared.u64 t, %1; cvt.u32.u64 %0, t; }" : "=r"(a) : "l"(p));
    return a;
}

// ------------------- conversion kernels -------------------
__global__ void k_cvthid(const float* __restrict__ h) {
    int i = (blockIdx.x * 256 + threadIdx.x) * 4;
    float4 v = *(const float4*)&h[i];
    __nv_bfloat162* o = (__nv_bfloat162*)&d_hidbf[i];
    o[0] = __floats2bfloat162_rn(v.x, v.y);
    o[1] = __floats2bfloat162_rn(v.z, v.w);
}

__global__ void k_cvtW(const float* __restrict__ W) {   // (768,1024) -> bf16 [1024][768]
    __shared__ float t[32][33];
    int k0 = blockIdx.y * 32, n0 = blockIdx.x * 32;
    int tx = threadIdx.x, ty = threadIdx.y;
    #pragma unroll
    for (int i = 0; i < 32; i += 8)
        t[ty + i][tx] = W[(size_t)(k0 + ty + i) * OUTD + n0 + tx];
    __syncthreads();
    #pragma unroll
    for (int i = 0; i < 32; i += 8)
        d_wbf[(size_t)(n0 + ty + i) * HH + k0 + tx] = __float2bfloat16(t[tx][ty + i]);
}

// --------- partial sums for global_feat (reads L2-hot bf16) + cover counts ---------
__global__ void k_gfpart(const int* __restrict__ spans) {
    int b = blockIdx.y, p = blockIdx.x;
    int tid = threadIdx.x;
    if (tid < 128) {
        int s = p * 128 + tid;
        const int* sp = spans + b * KSP * 3;
        float c = 0.f;
        #pragma unroll
        for (int k = 0; k < KSP; k++) {
            int st = sp[k * 3], en = sp[k * 3 + 1];
            c += (s >= st && s <= en) ? 1.f : 0.f;
        }
        d_cover[b * SS + s] = c;
    }
    for (int c = tid; c < HH; c += 256) {
        float acc = 0.f;
        const __nv_bfloat16* base = d_hidbf + ((size_t)b * SS + (size_t)p * 128) * HH + c;
        #pragma unroll 4
        for (int s = 0; s < 128; s++) acc += __bfloat162float(base[(size_t)s * HH]);
        d_gfpart[(b * 8 + p) * HH + c] = acc;
    }
}

// ------------------- GAT attention helper -------------------
__device__ __forceinline__ void gat_attn(const float* __restrict__ hmat,
                                         const float* __restrict__ avsrc,
                                         const float* __restrict__ avdst,
                                         const float* __restrict__ sAdj,
                                         float* sAS, float* sAD, float* sAttn, int tid) {
    if (tid < NN * NHEADS * 2) {
        int n = tid / (NHEADS * 2);
        int rem = tid % (NHEADS * 2);
        int head = rem % NHEADS;
        int isd = rem / NHEADS;
        const float* av = isd ? avdst : avsrc;
        float acc = 0.f;
        for (int f = 0; f < HIDD; f++) acc += hmat[n * FF + head * HIDD + f] * av[head * HIDD + f];
        if (isd) sAD[n * NHEADS + head] = acc;
        else     sAS[n * NHEADS + head] = acc;
    }
    __syncthreads();
    if (tid < NN * NHEADS) {
        int i = tid / NHEADS, head = tid % NHEADS;
        float sc[NN];
        float mx = -1e30f;
        #pragma unroll
        for (int j = 0; j < NN; j++) {
            float adj = sAdj[i * NN + j];
            float v;
            if (adj > 0.f) {
                float e = sAD[i * NHEADS + head] + sAS[j * NHEADS + head];
                e = (e >= 0.f) ? e : 0.2f * e;
                v = e + logf(adj);
            } else v = -1e30f;
            sc[j] = v;
            mx = fmaxf(mx, v);
        }
        float ssum = 0.f;
        #pragma unroll
        for (int j = 0; j < NN; j++) { float e = expf(sc[j] - mx); sc[j] = e; ssum += e; }
        float inv = 1.f / ssum;
        #pragma unroll
        for (int j = 0; j < NN; j++) sAttn[(i * NN + j) * NHEADS + head] = sc[j] * inv;
    }
    __syncthreads();
}

// ------------------- per-batch graph pipeline -------------------
__global__ void k_stage1(const float* __restrict__ hidden, const int* __restrict__ spans,
                         const float* __restrict__ W1, const float* __restrict__ asrc1,
                         const float* __restrict__ adst1, const float* __restrict__ b1,
                         const float* __restrict__ lng, const float* __restrict__ lnb,
                         const float* __restrict__ W2, const float* __restrict__ asrc2,
                         const float* __restrict__ adst2, const float* __restrict__ b2) {
    int b = blockIdx.x;
    int tid = threadIdx.x;
    __shared__ float sN[NN * HH];
    __shared__ float sH[NN * FF];
    __shared__ float sG[NN * FF];
    __shared__ float sAdj[NN * NN];
    __shared__ float sAS[NN * NHEADS], sAD[NN * NHEADS];
    __shared__ float sAttn[NN * NN * NHEADS];
    __shared__ int sSp[KSP * 2];
    __shared__ float sRed[2];
    __shared__ float sWred[16];

    if (tid < KSP * 2) {
        int k = tid / 2, w = tid % 2;
        sSp[tid] = spans[(b * KSP + k) * 3 + w];
    }
    __syncthreads();

    for (int c = tid; c < HH; c += 256) {
        float g = 0.f;
        #pragma unroll
        for (int p = 0; p < 8; p++) g += d_gfpart[(b * 8 + p) * HH + c];
        sN[c] = g * (1.f / (float)SS);
    }
    for (int k = 0; k < KSP; k++) {
        int st = sSp[k * 2], en = sSp[k * 2 + 1];
        float inv = 1.f / (float)(en - st + 1);
        for (int c = tid; c < HH; c += 256) {
            float a = 0.f;
            for (int s = st; s <= en; s++) a += hidden[((size_t)b * SS + s) * HH + c];
            sN[(1 + k) * HH + c] = a * inv;
        }
    }
    if (tid < NN * NN) {
        int r = tid / NN, c = tid % NN;
        float v = 0.f;
        if (r == c) v += 1.f;
        if (c == 0 && r >= 1) v += 1.f;
        if (r == 0 && c >= 1) v += 1.f;
        if (r >= 1 && c >= 1 && r != c) {
            int i = r - 1, j = c - 1;
            int si = sSp[i * 2], ei = sSp[i * 2 + 1];
            int sj = sSp[j * 2], ej = sSp[j * 2 + 1];
            bool same = (sj == si) && (ej == ei);
            if ((sj <= si) && (ei <= ej) && !same) v += 2.f;
        }
        sAdj[tid] = v;
    }
    __syncthreads();

    {
        float acc[NN];
        #pragma unroll
        for (int n = 0; n < NN; n++) acc[n] = 0.f;
        for (int d = 0; d < HH; d++) {
            float w = W1[d * FF + tid];
            #pragma unroll
            for (int n = 0; n < NN; n++) acc[n] += sN[n * HH + d] * w;
        }
        #pragma unroll
        for (int n = 0; n < NN; n++) sH[n * FF + tid] = acc[n];
    }
    __syncthreads();
    gat_attn(sH, asrc1, adst1, sAdj, sAS, sAD, sAttn, tid);
    {
        int head = tid / HIDD;
        for (int i = 0; i < NN; i++) {
            float acc = b1[tid];
            #pragma unroll
            for (int j = 0; j < NN; j++) acc += sAttn[(i * NN + j) * NHEADS + head] * sH[j * FF + tid];
            sG[i * FF + tid] = fmaxf(acc, 0.f);
        }
    }
    __syncthreads();
    for (int i = 0; i < NN; i++) {
        float v = sG[i * FF + tid];
        float s1 = v, s2 = v * v;
        #pragma unroll
        for (int o = 16; o > 0; o >>= 1) {
            s1 += __shfl_down_sync(0xffffffffu, s1, o);
            s2 += __shfl_down_sync(0xffffffffu, s2, o);
        }
        int wid = tid >> 5, lid = tid & 31;
        if (lid == 0) { sWred[wid] = s1; sWred[8 + wid] = s2; }
        __syncthreads();
        if (tid == 0) {
            float a = 0.f, q = 0.f;
            #pragma unroll
            for (int w = 0; w < 8; w++) { a += sWred[w]; q += sWred[8 + w]; }
            float mu = a / (float)FF;
            float var = q / (float)FF - mu * mu;
            sRed[0] = mu;
            sRed[1] = rsqrtf(var + 1e-5f);
        }
        __syncthreads();
        sG[i * FF + tid] = (v - sRed[0]) * sRed[1] * lng[tid] + lnb[tid];
        __syncthreads();
    }

    {
        float acc[NN];
        #pragma unroll
        for (int n = 0; n < NN; n++) acc[n] = 0.f;
        for (int d = 0; d < FF; d++) {
            float w = W2[d * FF + tid];
            #pragma unroll
            for (int n = 0; n < NN; n++) acc[n] += sG[n * FF + d] * w;
        }
        #pragma unroll
        for (int n = 0; n < NN; n++) sH[n * FF + tid] = acc[n];
    }
    __syncthreads();
    gat_attn(sH, asrc2, adst2, sAdj, sAS, sAD, sAttn, tid);
    {
        int head = tid / HIDD;
        float esum = 0.f;
        for (int i = 0; i < NN; i++) {
            float acc = b2[tid];
            #pragma unroll
            for (int j = 0; j < NN; j++) acc += sAttn[(i * NN + j) * NHEADS + head] * sH[j * FF + tid];
            esum += fmaxf(acc, 0.f);
        }
        d_enh[b * FF + tid] = esum * (1.f / (float)NN);
    }
}

// ------------------- eW = enhanced @ dense_W[768:1024,:] (wide grid) -------------------
__global__ void k_eW(const float* __restrict__ dW) {
    int b = blockIdx.y;
    int o = blockIdx.x * 128 + threadIdx.x;
    float acc = 0.f;
    #pragma unroll 8
    for (int c = 0; c < FF; c++)
        acc += d_enh[b * FF + c] * dW[(size_t)(HH + c) * OUTD + o];
    d_eW[b * OUTD + o] = acc;
}

// ------------------- bf16 MMA building blocks -------------------
__device__ __forceinline__ void g2s_fetch(uint4 (&pa)[2], uint4 (&pb)[2],
        const __nv_bfloat16* __restrict__ A, const __nv_bfloat16* __restrict__ B,
        int strA, int strB, int m0, int n0, int kk, int tid) {
    #pragma unroll
    for (int i = 0; i < 2; i++) {
        int lin = tid + i * 256;
        int row = lin >> 2, ch = lin & 3;
        pa[i] = *(const uint4*)(A + (size_t)(m0 + row) * strA + kk + ch * 8);
        pb[i] = *(const uint4*)(B + (size_t)(n0 + row) * strB + kk + ch * 8);
    }
}

__device__ __forceinline__ void s2s_store(uint4 (&pa)[2], uint4 (&pb)[2],
                                          uint4* dA, uint4* dB, int tid) {
    #pragma unroll
    for (int i = 0; i < 2; i++) {
        int lin = tid + i * 256;
        int row = lin >> 2, ch = lin & 3;
        int sw = ch ^ ((row >> 1) & 3);
        dA[row * 4 + sw] = pa[i];
        dB[row * 4 + sw] = pb[i];
    }
}

__device__ __forceinline__ void tile_compute(uint32_t baseA, uint32_t baseB,
                                             int wm0, int wn0, int lane,
                                             float (&acc)[4][4][4]) {
    int rowAo = lane & 15, chAo = lane >> 4;
    int rowBo = (lane & 7) + ((lane & 16) >> 1), chBo = (lane >> 3) & 1;
    #pragma unroll
    for (int ks = 0; ks < 2; ks++) {
        uint32_t a[4][4], b[2][4];
        #pragma unroll
        for (int mi = 0; mi < 4; mi++) {
            int row = wm0 + mi * 16 + rowAo;
            int ch = ks * 2 + chAo;
            uint32_t addr = baseA + row * 64 + ((ch ^ ((row >> 1) & 3)) << 4);
            asm volatile("ldmatrix.sync.aligned.m8n8.x4.shared.b16 {%0,%1,%2,%3}, [%4];"
                : "=r"(a[mi][0]), "=r"(a[mi][1]), "=r"(a[mi][2]), "=r"(a[mi][3]) : "r"(addr));
        }
        #pragma unroll
        for (int ng = 0; ng < 2; ng++) {
            int row = wn0 + ng * 16 + rowBo;
            int ch = ks * 2 + chBo;
            uint32_t addr = baseB + row * 64 + ((ch ^ ((row >> 1) & 3)) << 4);
            asm volatile("ldmatrix.sync.aligned.m8n8.x4.shared.b16 {%0,%1,%2,%3}, [%4];"
                : "=r"(b[ng][0]), "=r"(b[ng][1]), "=r"(b[ng][2]), "=r"(b[ng][3]) : "r"(addr));
        }
        #pragma unroll
        for (int mi = 0; mi < 4; mi++)
            #pragma unroll
            for (int ni = 0; ni < 4; ni++) {
                uint32_t b0 = b[ni >> 1][(ni & 1) * 2 + 0];
                uint32_t b1 = b[ni >> 1][(ni & 1) * 2 + 1];
                asm volatile("mma.sync.aligned.m16n8k16.row.col.f32.bf16.bf16.f32 "
                    "{%0,%1,%2,%3}, {%4,%5,%6,%7}, {%8,%9}, {%0,%1,%2,%3};"
                    : "+f"(acc[mi][ni][0]), "+f"(acc[mi][ni][1]),
                      "+f"(acc[mi][ni][2]), "+f"(acc[mi][ni][3])
                    : "r"(a[mi][0]), "r"(a[mi][1]), "r"(a[mi][2]), "r"(a[mi][3]),
                      "r"(b0), "r"(b1));
            }
    }
}

// ----- GEMM1 fused: qk = hid@W^T + cover*eW + db, RoPE, + gaussian extras -> q/k ext -----
__global__ void __launch_bounds__(256, 2) k_gemm1_mma(const float* __restrict__ db,
        const int* __restrict__ spans, const float* __restrict__ gc,
        const float* __restrict__ gs, const float* __restrict__ gw,
        const float* __restrict__ corr) {
    __shared__ uint4 sA[2][512], sB[2][512];
    int tid = threadIdx.x, lane = tid & 31, wid = tid >> 5;
    int m0 = blockIdx.y * 128, n0 = blockIdx.x * 128;
    int wm0 = (wid & 1) * 64, wn0 = (wid >> 1) * 32;
    float acc[4][4][4] = {};
    uint4 pa[2], pb[2];
    g2s_fetch(pa, pb, d_hidbf, d_wbf, HH, HH, m0, n0, 0, tid);
    s2s_store(pa, pb, sA[0], sB[0], tid);
    __syncthreads();
    const int NT = HH / 32;
    for (int it = 0; it < NT; ++it) {
        if (it + 1 < NT) g2s_fetch(pa, pb, d_hidbf, d_wbf, HH, HH, m0, n0, (it + 1) * 32, tid);
        tile_compute(smem_u32(sA[it & 1]), smem_u32(sB[it & 1]), wm0, wn0, lane, acc);
        if (it + 1 < NT) s2s_store(pa, pb, sA[(it + 1) & 1], sB[(it + 1) & 1], tid);
        __syncthreads();
    }
    int g = lane >> 2, tq = lane & 3;
    int t = blockIdx.x;   // 128-col tile == one t slice
    #pragma unroll
    for (int mi = 0; mi < 4; mi++) {
        #pragma unroll
        for (int half = 0; half < 2; half++) {
            int r = m0 + wm0 + mi * 16 + g + half * 8;
            int b = r >> 10, s = r & (SS - 1);
            float cov = d_cover[r];
            float sf = (float)s;
            size_t rowbase = ((size_t)(b * TT + t) * SS + s) * KEP;
            #pragma unroll
            for (int ni = 0; ni < 4; ni++) {
                int jj = wn0 + ni * 8 + tq * 2;   // even, 0..126
                int c = n0 + jj;
                float2 ew = *(const float2*)&d_eW[b * OUTD + c];
                float2 dbv = *(const float2*)&db[c];
                float x = acc[mi][ni][half * 2 + 0] + cov * ew.x + dbv.x;
                float y = acc[mi][ni][half * 2 + 1] + cov * ew.y + dbv.y;
                int i = (jj & 63) >> 1;
                float ang = sf * exp2f(-(float)i * L2C);
                float sv, cvv;
                sincosf(ang, &sv, &cvv);
                __nv_bfloat162 v = __floats2bfloat162_rn(x * cvv - y * sv, y * cvv + x * sv);
                __nv_bfloat16* dst = ((jj < 64) ? d_qext : d_kext) + rowbase + (jj & 63);
                *(__nv_bfloat162*)dst = v;
            }
        }
    }
    // ---- gaussian extras: cols 64..95, tid<128 -> q rows, tid>=128 -> k rows ----
    {
        int r = m0 + (tid & 127);
        int b = r >> 10, s = r & (SS - 1);
        bool isq = tid < 128;
        float sf = (float)s;
        const int* sp = spans + b * KSP * 3;
        float g0w = gw[0], g1w = gw[1];
        float g0c = gc[0], g1c = gc[1];
        float g0si = 1.f / gs[0], g1si = 1.f / gs[1];
        __nv_bfloat162* dst = (__nv_bfloat162*)(
            (isq ? d_qext : d_kext) + ((size_t)(b * TT + t) * SS + s) * KEP + 64);
        #pragma unroll
        for (int kk = 0; kk < KSP; kk++) {
            int st = sp[kk * 3], en = sp[kk * 3 + 1], et = sp[kk * 3 + 2];
            float base = isq ? (float)st : (float)en;
            float mult = isq ? corr[et * TT + t] : 1.f;
            float d0 = (sf - base - g0c) * g0si;
            float d1 = (sf - base - g1c) * g1si;
            dst[kk] = __floats2bfloat162_rn(mult * g0w * expf(-0.5f * d0 * d0),
                                            mult * g1w * expf(-0.5f * d1 * d1));
        }
        __nv_bfloat162 z = __floats2bfloat162_rn(0.f, 0.f);
        #pragma unroll
        for (int i = 8; i < 16; i++) dst[i] = z;
    }
}

// ------------- GEMM2: logits (batched 1024x1024x96) + mask epilogue + tril skip -------------
__global__ void __launch_bounds__(256, 2) k_gemm2_mma(const float* __restrict__ mask,
                                                      float* __restrict__ out) {
    __shared__ uint4 sA[2][512], sB[2][512];
    int bt = blockIdx.z;
    int b = bt >> 3;
    int tid = threadIdx.x;
    int m0 = blockIdx.y * 128, n0 = blockIdx.x * 128;

    if (m0 > n0) {
        // fully below the diagonal: logits contribution (|v|<~1e3) is negligible vs -1e12
        int colq = (tid & 31) * 4;
        float4 pd = *(const float4*)&mask[b * SS + n0 + colq];
        float4 v;
        v.x = (-(1.f - pd.x) * NEGC - NEGC) * 0.125f;
        v.y = (-(1.f - pd.y) * NEGC - NEGC) * 0.125f;
        v.z = (-(1.f - pd.z) * NEGC - NEGC) * 0.125f;
        v.w = (-(1.f - pd.w) * NEGC - NEGC) * 0.125f;
        int r0 = tid >> 5;
        #pragma unroll
        for (int p = 0; p < 16; p++) {
            int m = m0 + p * 8 + r0;
            *(float4*)&out[((size_t)bt * SS + m) * SS + n0 + colq] = v;
        }
        return;
    }

    const __nv_bfloat16* Ab = d_qext + (size_t)bt * SS * KEP;
    const __nv_bfloat16* Bb = d_kext + (size_t)bt * SS * KEP;
    int lane = tid & 31, wid = tid >> 5;
    int wm0 = (wid & 1) * 64, wn0 = (wid >> 1) * 32;
    float acc[4][4][4] = {};
    uint4 pa[2], pb[2];
    g2s_fetch(pa, pb, Ab, Bb, KEP, KEP, m0, n0, 0, tid);
    s2s_store(pa, pb, sA[0], sB[0], tid);
    __syncthreads();
    const int NT = KEP / 32;
    for (int it = 0; it < NT; ++it) {
        if (it + 1 < NT) g2s_fetch(pa, pb, Ab, Bb, KEP, KEP, m0, n0, (it + 1) * 32, tid);
        tile_compute(smem_u32(sA[it & 1]), smem_u32(sB[it & 1]), wm0, wn0, lane, acc);
        if (it + 1 < NT) s2s_store(pa, pb, sA[(it + 1) & 1], sB[(it + 1) & 1], tid);
        __syncthreads();
    }
    int g = lane >> 2, tq = lane & 3;
    #pragma unroll
    for (int mi = 0; mi < 4; mi++) {
        #pragma unroll
        for (int half = 0; half < 2; half++) {
            int m = m0 + wm0 + mi * 16 + g + half * 8;
            #pragma unroll
            for (int ni = 0; ni < 4; ni++) {
                int n = n0 + wn0 + ni * 8 + tq * 2;
                float2 pd = *(const float2*)&mask[b * SS + n];
                float v0 = acc[mi][ni][half * 2 + 0] * pd.x - (1.f - pd.x) * NEGC;
                float v1 = acc[mi][ni][half * 2 + 1] * pd.y - (1.f - pd.y) * NEGC;
                if (m > n)     v0 -= NEGC;
                if (m > n + 1) v1 -= NEGC;
                float2 res;
                res.x = v0 * 0.125f;
                res.y = v1 * 0.125f;
                *(float2*)&out[((size_t)bt * SS + m) * SS + n] = res;
            }
        }
    }
}

// ------------------- launch -------------------
extern "C" void kernel_launch(void* const* d_in, const int* in_sizes, int n_in,
                              void* d_out, int out_size) {
    const float* hidden = (const float*)d_in[0];
    const float* amask  = (const float*)d_in[1];
    const int*   spans  = (const int*)d_in[2];
    const float* W1     = (const float*)d_in[3];
    const float* asrc1  = (const float*)d_in[4];
    const float* adst1  = (const float*)d_in[5];
    const float* b1     = (const float*)d_in[6];
    const float* lng    = (const float*)d_in[7];
    const float* lnb    = (const float*)d_in[8];
    const float* W2     = (const float*)d_in[9];
    const float* asrc2  = (const float*)d_in[10];
    const float* adst2  = (const float*)d_in[11];
    const float* b2     = (const float*)d_in[12];
    const float* dW     = (const float*)d_in[13];
    const float* db     = (const float*)d_in[14];
    const float* gc     = (const float*)d_in[15];
    const float* gsg    = (const float*)d_in[16];
    const float* gwt    = (const float*)d_in[17];
    const float* corr   = (const float*)d_in[18];
    float* out = (float*)d_out;

    k_cvthid<<<(BB * SS * HH) / 1024, 256>>>(hidden);
    k_cvtW<<<dim3(OUTD / 32, HH / 32), dim3(32, 8)>>>(dW);
    k_gfpart<<<dim3(8, BB), 256>>>(spans);
    k_stage1<<<BB, 256>>>(hidden, spans, W1, asrc1, adst1, b1, lng, lnb,
                          W2, asrc2, adst2, b2);
    k_eW<<<dim3(OUTD / 128, BB), 128>>>(dW);
    k_gemm1_mma<<<dim3(OUTD / 128, (BB * SS) / 128), 256>>>(db, spans, gc, gsg, gwt, corr);
    k_gemm2_mma<<<dim3(SS / 128, SS / 128, BB * TT), 256>>>(amask, out);
}

// round 7
// speedup vs baseline: 3.6195x; 1.3634x over previous
#include <cuda_runtime.h>
#include <cuda_bf16.h>
#include <math.h>
#include <cstdint>
#include <cstddef>

#define BB 8
#define SS 1024
#define HH 768
#define TT 8
#define DDI 64
#define HIDD 128
#define KSP 8
#define NHEADS 2
#define NN 9
#define FF 256      // NHEADS*HIDD
#define OUTD 1024   // TT*2*DDI
#define KEP 96      // 64 rope + 16 gaussian + 16 zero pad
#define NEGC 1000000000000.0f
#define L2C 0.41524101186092573f   // log2(10000)/32

// ------------------- device scratch -------------------
__device__ float d_gfpart[BB * 8 * HH];
__device__ float d_nodes[BB * NN * HH];
__device__ float d_h1[BB * NN * FF];
__device__ float d_as1[BB * NN * NHEADS], d_ad1[BB * NN * NHEADS];
__device__ float d_g1[BB * NN * FF];
__device__ float d_h2[BB * NN * FF];
__device__ float d_as2[BB * NN * NHEADS], d_ad2[BB * NN * NHEADS];
__device__ float d_enh[BB * FF];
__device__ float d_eW[BB * OUTD];
__device__ float d_cover[BB * SS];
__device__ __nv_bfloat16 d_hidbf[(size_t)BB * SS * HH];
__device__ __nv_bfloat16 d_wbf[(size_t)OUTD * HH];               // W^T bf16 [n][k]
__device__ __nv_bfloat16 d_qext[(size_t)BB * TT * SS * KEP];
__device__ __nv_bfloat16 d_kext[(size_t)BB * TT * SS * KEP];

__device__ __forceinline__ uint32_t smem_u32(const void* p) {
    uint32_t a;
    asm("{ .reg .u64 t; cvta.to.shared.u64 t, %1; cvt.u32.u64 %0, t; }" : "=r"(a) : "l"(p));
    return a;
}

// ------------------- conversion kernels -------------------
__global__ void k_cvthid(const float* __restrict__ h) {
    int i = (blockIdx.x * 256 + threadIdx.x) * 4;
    float4 v = *(const float4*)&h[i];
    __nv_bfloat162* o = (__nv_bfloat162*)&d_hidbf[i];
    o[0] = __floats2bfloat162_rn(v.x, v.y);
    o[1] = __floats2bfloat162_rn(v.z, v.w);
}

__global__ void k_cvtW(const float* __restrict__ W) {   // (768,1024) -> bf16 [1024][768]
    __shared__ float t[32][33];
    int k0 = blockIdx.y * 32, n0 = blockIdx.x * 32;
    int tx = threadIdx.x, ty = threadIdx.y;
    #pragma unroll
    for (int i = 0; i < 32; i += 8)
        t[ty + i][tx] = W[(size_t)(k0 + ty + i) * OUTD + n0 + tx];
    __syncthreads();
    #pragma unroll
    for (int i = 0; i < 32; i += 8)
        d_wbf[(size_t)(n0 + ty + i) * HH + k0 + tx] = __float2bfloat16(t[tx][ty + i]);
}

// --------- partial sums for global_feat (reads L2-hot bf16) + cover counts ---------
__global__ void k_gfpart(const int* __restrict__ spans) {
    int b = blockIdx.y, p = blockIdx.x;
    int tid = threadIdx.x;
    if (tid < 128) {
        int s = p * 128 + tid;
        const int* sp = spans + b * KSP * 3;
        float c = 0.f;
        #pragma unroll
        for (int k = 0; k < KSP; k++) {
            int st = sp[k * 3], en = sp[k * 3 + 1];
            c += (s >= st && s <= en) ? 1.f : 0.f;
        }
        d_cover[b * SS + s] = c;
    }
    for (int c = tid; c < HH; c += 256) {
        float acc = 0.f;
        const __nv_bfloat16* base = d_hidbf + ((size_t)b * SS + (size_t)p * 128) * HH + c;
        #pragma unroll 4
        for (int s = 0; s < 128; s++) acc += __bfloat162float(base[(size_t)s * HH]);
        d_gfpart[(b * 8 + p) * HH + c] = acc;
    }
}

// ------------------- node features (global mean + span means) -------------------
__global__ void k_nodes(const float* __restrict__ hidden, const int* __restrict__ spans) {
    int n = blockIdx.x, b = blockIdx.y;
    int tid = threadIdx.x;
    float* dst = d_nodes + (b * NN + n) * HH;
    if (n == 0) {
        for (int c = tid; c < HH; c += 256) {
            float g = 0.f;
            #pragma unroll
            for (int p = 0; p < 8; p++) g += d_gfpart[(b * 8 + p) * HH + c];
            dst[c] = g * (1.f / (float)SS);
        }
    } else {
        int k = n - 1;
        int st = spans[(b * KSP + k) * 3 + 0];
        int en = spans[(b * KSP + k) * 3 + 1];
        float inv = 1.f / (float)(en - st + 1);
        for (int c = tid; c < HH; c += 256) {
            float a = 0.f;
            for (int s = st; s <= en; s++) a += hidden[((size_t)b * SS + s) * HH + c];
            dst[c] = a * inv;
        }
    }
}

// ------- per-node linear: h = node @ W (K = KDIM) + a_src/a_dst reductions -------
template <int KDIM>
__device__ __forceinline__ void node_linear(const float* __restrict__ x,
        const float* __restrict__ W, const float* __restrict__ avsrc,
        const float* __restrict__ avdst, float* __restrict__ outH,
        float* __restrict__ outAS, float* __restrict__ outAD, int bn) {
    __shared__ float sX[KDIM];
    __shared__ float rS[8], rD[8];
    int tid = threadIdx.x;
    for (int c = tid; c < KDIM; c += 256) sX[c] = x[c];
    __syncthreads();
    float acc = 0.f;
    #pragma unroll 8
    for (int d = 0; d < KDIM; d++) acc += sX[d] * W[(size_t)d * FF + tid];
    outH[tid] = acc;
    int head = tid >> 7, dd = tid & 127;
    float vs = acc * avsrc[head * HIDD + dd];
    float vd = acc * avdst[head * HIDD + dd];
    #pragma unroll
    for (int o = 16; o > 0; o >>= 1) {
        vs += __shfl_down_sync(0xffffffffu, vs, o);
        vd += __shfl_down_sync(0xffffffffu, vd, o);
    }
    int wid = tid >> 5, lane = tid & 31;
    if (lane == 0) { rS[wid] = vs; rD[wid] = vd; }
    __syncthreads();
    if (tid < 2) {
        float s = 0.f, d2 = 0.f;
        #pragma unroll
        for (int w = 0; w < 4; w++) { s += rS[tid * 4 + w]; d2 += rD[tid * 4 + w]; }
        outAS[bn * NHEADS + tid] = s;
        outAD[bn * NHEADS + tid] = d2;
    }
}

__global__ void k_h1(const float* __restrict__ W1, const float* __restrict__ asrc1,
                     const float* __restrict__ adst1) {
    int n = blockIdx.x, b = blockIdx.y;
    int bn = b * NN + n;
    node_linear<HH>(d_nodes + bn * HH, W1, asrc1, adst1,
                    d_h1 + bn * FF, d_as1, d_ad1, bn);
}

__global__ void k_h2(const float* __restrict__ W2, const float* __restrict__ asrc2,
                     const float* __restrict__ adst2) {
    int n = blockIdx.x, b = blockIdx.y;
    int bn = b * NN + n;
    node_linear<FF>(d_g1 + bn * FF, W2, asrc2, adst2,
                    d_h2 + bn * FF, d_as2, d_ad2, bn);
}

// ------------------- adjacency + attention softmax (in-block) -------------------
__device__ __forceinline__ void build_adj_attn(const int* __restrict__ spans, int b,
        const float* __restrict__ gAS, const float* __restrict__ gAD,
        float* sAdj, float* sAS, float* sAD, float* sAttn, int* sSp, int tid) {
    if (tid < KSP * 2) sSp[tid] = spans[(b * KSP + tid / 2) * 3 + (tid & 1)];
    if (tid >= 32 && tid - 32 < NN * NHEADS) {
        sAS[tid - 32] = gAS[b * NN * NHEADS + tid - 32];
        sAD[tid - 32] = gAD[b * NN * NHEADS + tid - 32];
    }
    __syncthreads();
    if (tid < NN * NN) {
        int r = tid / NN, c = tid % NN;
        float v = 0.f;
        if (r == c) v += 1.f;
        if (c == 0 && r >= 1) v += 1.f;
        if (r == 0 && c >= 1) v += 1.f;
        if (r >= 1 && c >= 1 && r != c) {
            int i = r - 1, j = c - 1;
            int si = sSp[i * 2], ei = sSp[i * 2 + 1];
            int sj = sSp[j * 2], ej = sSp[j * 2 + 1];
            bool same = (sj == si) && (ej == ei);
            if ((sj <= si) && (ei <= ej) && !same) v += 2.f;
        }
        sAdj[tid] = v;
    }
    __syncthreads();
    if (tid < NN * NHEADS) {
        int i = tid / NHEADS, head = tid % NHEADS;
        float sc[NN];
        float mx = -1e30f;
        #pragma unroll
        for (int j = 0; j < NN; j++) {
            float adj = sAdj[i * NN + j];
            float v;
            if (adj > 0.f) {
                float e = sAD[i * NHEADS + head] + sAS[j * NHEADS + head];
                e = (e >= 0.f) ? e : 0.2f * e;
                v = e + logf(adj);
            } else v = -1e30f;
            sc[j] = v;
            mx = fmaxf(mx, v);
        }
        float ssum = 0.f;
        #pragma unroll
        for (int j = 0; j < NN; j++) { float e = expf(sc[j] - mx); sc[j] = e; ssum += e; }
        float inv = 1.f / ssum;
        #pragma unroll
        for (int j = 0; j < NN; j++) sAttn[(i * NN + j) * NHEADS + head] = sc[j] * inv;
    }
    __syncthreads();
}

// ------------------- GAT layer 1 tail: attn @ h1 + relu + LN -> g1 -------------------
__global__ void k_gat1(const int* __restrict__ spans, const float* __restrict__ b1,
                       const float* __restrict__ lng, const float* __restrict__ lnb) {
    int b = blockIdx.x, tid = threadIdx.x;
    __shared__ float sH[NN * FF], sG[NN * FF];
    __shared__ float sAdj[NN * NN], sAS[NN * NHEADS], sAD[NN * NHEADS];
    __shared__ float sAttn[NN * NN * NHEADS];
    __shared__ int sSp[KSP * 2];
    __shared__ float sWred[16], sRed[2];
    for (int i = tid; i < NN * FF; i += 256) sH[i] = d_h1[b * NN * FF + i];
    build_adj_attn(spans, b, d_as1, d_ad1, sAdj, sAS, sAD, sAttn, sSp, tid);
    {
        int head = tid / HIDD;
        float bb = b1[tid];
        #pragma unroll
        for (int i = 0; i < NN; i++) {
            float acc = bb;
            #pragma unroll
            for (int j = 0; j < NN; j++) acc += sAttn[(i * NN + j) * NHEADS + head] * sH[j * FF + tid];
            sG[i * FF + tid] = fmaxf(acc, 0.f);
        }
    }
    __syncthreads();
    float gw = lng[tid], gb = lnb[tid];
    for (int i = 0; i < NN; i++) {
        float v = sG[i * FF + tid];
        float s1 = v, s2 = v * v;
        #pragma unroll
        for (int o = 16; o > 0; o >>= 1) {
            s1 += __shfl_down_sync(0xffffffffu, s1, o);
            s2 += __shfl_down_sync(0xffffffffu, s2, o);
        }
        int wid = tid >> 5, lane = tid & 31;
        if (lane == 0) { sWred[wid] = s1; sWred[8 + wid] = s2; }
        __syncthreads();
        if (tid == 0) {
            float a = 0.f, q = 0.f;
            #pragma unroll
            for (int w = 0; w < 8; w++) { a += sWred[w]; q += sWred[8 + w]; }
            float mu = a / (float)FF;
            float var = q / (float)FF - mu * mu;
            sRed[0] = mu;
            sRed[1] = rsqrtf(var + 1e-5f);
        }
        __syncthreads();
        d_g1[b * NN * FF + i * FF + tid] = (v - sRed[0]) * sRed[1] * gw + gb;
        __syncthreads();
    }
}

// ------------------- GAT layer 2 tail: attn @ h2 + relu, mean -> enh -------------------
__global__ void k_gat2(const int* __restrict__ spans, const float* __restrict__ b2) {
    int b = blockIdx.x, tid = threadIdx.x;
    __shared__ float sH[NN * FF];
    __shared__ float sAdj[NN * NN], sAS[NN * NHEADS], sAD[NN * NHEADS];
    __shared__ float sAttn[NN * NN * NHEADS];
    __shared__ int sSp[KSP * 2];
    for (int i = tid; i < NN * FF; i += 256) sH[i] = d_h2[b * NN * FF + i];
    build_adj_attn(spans, b, d_as2, d_ad2, sAdj, sAS, sAD, sAttn, sSp, tid);
    {
        int head = tid / HIDD;
        float bb = b2[tid];
        float esum = 0.f;
        #pragma unroll
        for (int i = 0; i < NN; i++) {
            float acc = bb;
            #pragma unroll
            for (int j = 0; j < NN; j++) acc += sAttn[(i * NN + j) * NHEADS + head] * sH[j * FF + tid];
            esum += fmaxf(acc, 0.f);
        }
        d_enh[b * FF + tid] = esum * (1.f / (float)NN);
    }
}

// ------------------- eW = enhanced @ dense_W[768:1024,:] -------------------
__global__ void k_eW(const float* __restrict__ dW) {
    int b = blockIdx.y;
    int o = blockIdx.x * 128 + threadIdx.x;
    float acc = 0.f;
    #pragma unroll 8
    for (int c = 0; c < FF; c++)
        acc += d_enh[b * FF + c] * dW[(size_t)(HH + c) * OUTD + o];
    d_eW[b * OUTD + o] = acc;
}

// ------------------- bf16 MMA building blocks -------------------
__device__ __forceinline__ void g2s_fetch(uint4 (&pa)[2], uint4 (&pb)[2],
        const __nv_bfloat16* __restrict__ A, const __nv_bfloat16* __restrict__ B,
        int strA, int strB, int m0, int n0, int kk, int tid) {
    #pragma unroll
    for (int i = 0; i < 2; i++) {
        int lin = tid + i * 256;
        int row = lin >> 2, ch = lin & 3;
        pa[i] = *(const uint4*)(A + (size_t)(m0 + row) * strA + kk + ch * 8);
        pb[i] = *(const uint4*)(B + (size_t)(n0 + row) * strB + kk + ch * 8);
    }
}

__device__ __forceinline__ void s2s_store(uint4 (&pa)[2], uint4 (&pb)[2],
                                          uint4* dA, uint4* dB, int tid) {
    #pragma unroll
    for (int i = 0; i < 2; i++) {
        int lin = tid + i * 256;
        int row = lin >> 2, ch = lin & 3;
        int sw = ch ^ ((row >> 1) & 3);
        dA[row * 4 + sw] = pa[i];
        dB[row * 4 + sw] = pb[i];
    }
}

__device__ __forceinline__ void tile_compute(uint32_t baseA, uint32_t baseB,
                                             int wm0, int wn0, int lane,
                                             float (&acc)[4][4][4]) {
    int rowAo = lane & 15, chAo = lane >> 4;
    int rowBo = (lane & 7) + ((lane & 16) >> 1), chBo = (lane >> 3) & 1;
    #pragma unroll
    for (int ks = 0; ks < 2; ks++) {
        uint32_t a[4][4], b[2][4];
        #pragma unroll
        for (int mi = 0; mi < 4; mi++) {
            int row = wm0 + mi * 16 + rowAo;
            int ch = ks * 2 + chAo;
            uint32_t addr = baseA + row * 64 + ((ch ^ ((row >> 1) & 3)) << 4);
            asm volatile("ldmatrix.sync.aligned.m8n8.x4.shared.b16 {%0,%1,%2,%3}, [%4];"
                : "=r"(a[mi][0]), "=r"(a[mi][1]), "=r"(a[mi][2]), "=r"(a[mi][3]) : "r"(addr));
        }
        #pragma unroll
        for (int ng = 0; ng < 2; ng++) {
            int row = wn0 + ng * 16 + rowBo;
            int ch = ks * 2 + chBo;
            uint32_t addr = baseB + row * 64 + ((ch ^ ((row >> 1) & 3)) << 4);
            asm volatile("ldmatrix.sync.aligned.m8n8.x4.shared.b16 {%0,%1,%2,%3}, [%4];"
                : "=r"(b[ng][0]), "=r"(b[ng][1]), "=r"(b[ng][2]), "=r"(b[ng][3]) : "r"(addr));
        }
        #pragma unroll
        for (int mi = 0; mi < 4; mi++)
            #pragma unroll
            for (int ni = 0; ni < 4; ni++) {
                uint32_t b0 = b[ni >> 1][(ni & 1) * 2 + 0];
                uint32_t b1 = b[ni >> 1][(ni & 1) * 2 + 1];
                asm volatile("mma.sync.aligned.m16n8k16.row.col.f32.bf16.bf16.f32 "
                    "{%0,%1,%2,%3}, {%4,%5,%6,%7}, {%8,%9}, {%0,%1,%2,%3};"
                    : "+f"(acc[mi][ni][0]), "+f"(acc[mi][ni][1]),
                      "+f"(acc[mi][ni][2]), "+f"(acc[mi][ni][3])
                    : "r"(a[mi][0]), "r"(a[mi][1]), "r"(a[mi][2]), "r"(a[mi][3]),
                      "r"(b0), "r"(b1));
            }
    }
}

// ----- GEMM1 fused: qk = hid@W^T + cover*eW + db, RoPE, + gaussian extras -> q/k ext -----
__global__ void __launch_bounds__(256, 2) k_gemm1_mma(const float* __restrict__ db,
        const int* __restrict__ spans, const float* __restrict__ gc,
        const float* __restrict__ gs, const float* __restrict__ gw,
        const float* __restrict__ corr) {
    __shared__ uint4 sA[2][512], sB[2][512];
    int tid = threadIdx.x, lane = tid & 31, wid = tid >> 5;
    int m0 = blockIdx.y * 128, n0 = blockIdx.x * 128;
    int wm0 = (wid & 1) * 64, wn0 = (wid >> 1) * 32;
    float acc[4][4][4] = {};
    uint4 pa[2], pb[2];
    g2s_fetch(pa, pb, d_hidbf, d_wbf, HH, HH, m0, n0, 0, tid);
    s2s_store(pa, pb, sA[0], sB[0], tid);
    __syncthreads();
    const int NT = HH / 32;
    for (int it = 0; it < NT; ++it) {
        if (it + 1 < NT) g2s_fetch(pa, pb, d_hidbf, d_wbf, HH, HH, m0, n0, (it + 1) * 32, tid);
        tile_compute(smem_u32(sA[it & 1]), smem_u32(sB[it & 1]), wm0, wn0, lane, acc);
        if (it + 1 < NT) s2s_store(pa, pb, sA[(it + 1) & 1], sB[(it + 1) & 1], tid);
        __syncthreads();
    }
    int g = lane >> 2, tq = lane & 3;
    int t = blockIdx.x;   // 128-col tile == one t slice
    #pragma unroll
    for (int mi = 0; mi < 4; mi++) {
        #pragma unroll
        for (int half = 0; half < 2; half++) {
            int r = m0 + wm0 + mi * 16 + g + half * 8;
            int b = r >> 10, s = r & (SS - 1);
            float cov = d_cover[r];
            float sf = (float)s;
            size_t rowbase = ((size_t)(b * TT + t) * SS + s) * KEP;
            #pragma unroll
            for (int ni = 0; ni < 4; ni++) {
                int jj = wn0 + ni * 8 + tq * 2;   // even, 0..126
                int c = n0 + jj;
                float2 ew = *(const float2*)&d_eW[b * OUTD + c];
                float2 dbv = *(const float2*)&db[c];
                float x = acc[mi][ni][half * 2 + 0] + cov * ew.x + dbv.x;
                float y = acc[mi][ni][half * 2 + 1] + cov * ew.y + dbv.y;
                int i = (jj & 63) >> 1;
                float ang = sf * exp2f(-(float)i * L2C);
                float sv, cvv;
                sincosf(ang, &sv, &cvv);
                __nv_bfloat162 v = __floats2bfloat162_rn(x * cvv - y * sv, y * cvv + x * sv);
                __nv_bfloat16* dst = ((jj < 64) ? d_qext : d_kext) + rowbase + (jj & 63);
                *(__nv_bfloat162*)dst = v;
            }
        }
    }
    // ---- gaussian extras: cols 64..95, tid<128 -> q rows, tid>=128 -> k rows ----
    {
        int r = m0 + (tid & 127);
        int b = r >> 10, s = r & (SS - 1);
        bool isq = tid < 128;
        float sf = (float)s;
        const int* sp = spans + b * KSP * 3;
        float g0w = gw[0], g1w = gw[1];
        float g0c = gc[0], g1c = gc[1];
        float g0si = 1.f / gs[0], g1si = 1.f / gs[1];
        __nv_bfloat162* dst = (__nv_bfloat162*)(
            (isq ? d_qext : d_kext) + ((size_t)(b * TT + t) * SS + s) * KEP + 64);
        #pragma unroll
        for (int kk = 0; kk < KSP; kk++) {
            int st = sp[kk * 3], en = sp[kk * 3 + 1], et = sp[kk * 3 + 2];
            float base = isq ? (float)st : (float)en;
            float mult = isq ? corr[et * TT + t] : 1.f;
            float d0 = (sf - base - g0c) * g0si;
            float d1 = (sf - base - g1c) * g1si;
            dst[kk] = __floats2bfloat162_rn(mult * g0w * expf(-0.5f * d0 * d0),
                                            mult * g1w * expf(-0.5f * d1 * d1));
        }
        __nv_bfloat162 z = __floats2bfloat162_rn(0.f, 0.f);
        #pragma unroll
        for (int i = 8; i < 16; i++) dst[i] = z;
    }
}

// ------------- GEMM2: logits (batched 1024x1024x96) + mask epilogue + tril skip -------------
__global__ void __launch_bounds__(256, 2) k_gemm2_mma(const float* __restrict__ mask,
                                                      float* __restrict__ out) {
    __shared__ uint4 sA[2][512], sB[2][512];
    int bt = blockIdx.z;
    int b = bt >> 3;
    int tid = threadIdx.x;
    int m0 = blockIdx.y * 128, n0 = blockIdx.x * 128;

    if (m0 > n0) {
        int colq = (tid & 31) * 4;
        float4 pd = *(const float4*)&mask[b * SS + n0 + colq];
        float4 v;
        v.x = (-(1.f - pd.x) * NEGC - NEGC) * 0.125f;
        v.y = (-(1.f - pd.y) * NEGC - NEGC) * 0.125f;
        v.z = (-(1.f - pd.z) * NEGC - NEGC) * 0.125f;
        v.w = (-(1.f - pd.w) * NEGC - NEGC) * 0.125f;
        int r0 = tid >> 5;
        #pragma unroll
        for (int p = 0; p < 16; p++) {
            int m = m0 + p * 8 + r0;
            *(float4*)&out[((size_t)bt * SS + m) * SS + n0 + colq] = v;
        }
        return;
    }

    const __nv_bfloat16* Ab = d_qext + (size_t)bt * SS * KEP;
    const __nv_bfloat16* Bb = d_kext + (size_t)bt * SS * KEP;
    int lane = tid & 31, wid = tid >> 5;
    int wm0 = (wid & 1) * 64, wn0 = (wid >> 1) * 32;
    float acc[4][4][4] = {};
    uint4 pa[2], pb[2];
    g2s_fetch(pa, pb, Ab, Bb, KEP, KEP, m0, n0, 0, tid);
    s2s_store(pa, pb, sA[0], sB[0], tid);
    __syncthreads();
    const int NT = KEP / 32;
    for (int it = 0; it < NT; ++it) {
        if (it + 1 < NT) g2s_fetch(pa, pb, Ab, Bb, KEP, KEP, m0, n0, (it + 1) * 32, tid);
        tile_compute(smem_u32(sA[it & 1]), smem_u32(sB[it & 1]), wm0, wn0, lane, acc);
        if (it + 1 < NT) s2s_store(pa, pb, sA[(it + 1) & 1], sB[(it + 1) & 1], tid);
        __syncthreads();
    }
    int g = lane >> 2, tq = lane & 3;
    #pragma unroll
    for (int mi = 0; mi < 4; mi++) {
        #pragma unroll
        for (int half = 0; half < 2; half++) {
            int m = m0 + wm0 + mi * 16 + g + half * 8;
            #pragma unroll
            for (int ni = 0; ni < 4; ni++) {
                int n = n0 + wn0 + ni * 8 + tq * 2;
                float2 pd = *(const float2*)&mask[b * SS + n];
                float v0 = acc[mi][ni][half * 2 + 0] * pd.x - (1.f - pd.x) * NEGC;
                float v1 = acc[mi][ni][half * 2 + 1] * pd.y - (1.f - pd.y) * NEGC;
                if (m > n)     v0 -= NEGC;
                if (m > n + 1) v1 -= NEGC;
                float2 res;
                res.x = v0 * 0.125f;
                res.y = v1 * 0.125f;
                *(float2*)&out[((size_t)bt * SS + m) * SS + n] = res;
            }
        }
    }
}

// ------------------- launch -------------------
extern "C" void kernel_launch(void* const* d_in, const int* in_sizes, int n_in,
                              void* d_out, int out_size) {
    const float* hidden = (const float*)d_in[0];
    const float* amask  = (const float*)d_in[1];
    const int*   spans  = (const int*)d_in[2];
    const float* W1     = (const float*)d_in[3];
    const float* asrc1  = (const float*)d_in[4];
    const float* adst1  = (const float*)d_in[5];
    const float* b1     = (const float*)d_in[6];
    const float* lng    = (const float*)d_in[7];
    const float* lnb    = (const float*)d_in[8];
    const float* W2     = (const float*)d_in[9];
    const float* asrc2  = (const float*)d_in[10];
    const float* adst2  = (const float*)d_in[11];
    const float* b2     = (const float*)d_in[12];
    const float* dW     = (const float*)d_in[13];
    const float* db     = (const float*)d_in[14];
    const float* gc     = (const float*)d_in[15];
    const float* gsg    = (const float*)d_in[16];
    const float* gwt    = (const float*)d_in[17];
    const float* corr   = (const float*)d_in[18];
    float* out = (float*)d_out;

    k_cvthid<<<(BB * SS * HH) / 1024, 256>>>(hidden);
    k_cvtW<<<dim3(OUTD / 32, HH / 32), dim3(32, 8)>>>(dW);
    k_gfpart<<<dim3(8, BB), 256>>>(spans);
    k_nodes<<<dim3(NN, BB), 256>>>(hidden, spans);
    k_h1<<<dim3(NN, BB), 256>>>(W1, asrc1, adst1);
    k_gat1<<<BB, 256>>>(spans, b1, lng, lnb);
    k_h2<<<dim3(NN, BB), 256>>>(W2, asrc2, adst2);
    k_gat2<<<BB, 256>>>(spans, b2);
    k_eW<<<dim3(OUTD / 128, BB), 128>>>(dW);
    k_gemm1_mma<<<dim3(OUTD / 128, (BB * SS) / 128), 256>>>(db, spans, gc, gsg, gwt, corr);
    k_gemm2_mma<<<dim3(SS / 128, SS / 128, BB * TT), 256>>>(amask, out);
}